// round 1
// baseline (speedup 1.0000x reference)
#include <cuda_runtime.h>
#include <math.h>

// ---------------------------------------------------------------------------
// Problem constants
// ---------------------------------------------------------------------------
#define TABLE_NUM 16
#define STYLE_DIM 512
#define SAMPLE_RES 256
#define CH 32              // TABLE_NUM * 2
#define CMID 128           // CH * 4
#define TABLE_DIM 65536
#define BATCH 8
#define NPIX 65536         // 256*256
#define PRIME 2654435761u

// ---------------------------------------------------------------------------
// Scratch (device globals; no runtime allocation allowed)
// ---------------------------------------------------------------------------
__device__ float g_x  [(size_t)BATCH * CH   * NPIX];  // modulated conv1 input (b,c,p)
__device__ float g_y1 [(size_t)BATCH * CMID * NPIX];  // conv1 out * st2 (b,c,p)
__device__ float g_tok[(size_t)BATCH * CH   * NPIX];  // conv2 out (b,c,p)
__device__ float g_st1[BATCH * CH];
__device__ float g_st2[BATCH * CMID];
__device__ float g_d1 [BATCH * CMID];
__device__ float g_d2 [BATCH * CH];

struct ResArr { int r[16]; };

// ---------------------------------------------------------------------------
// Styles:   st = s @ (w_aff / sqrt(512)) + b_aff
// ---------------------------------------------------------------------------
__global__ void styles_kernel(const float* __restrict__ s,
                              const float* __restrict__ w1a, const float* __restrict__ b1a,
                              const float* __restrict__ w2a, const float* __restrict__ b2a)
{
    int b = blockIdx.x;
    int t = threadIdx.x;
    float inv = 1.0f / sqrtf(512.0f);
    const float* sb = s + b * STYLE_DIM;
    if (t < CH) {
        float acc = 0.f;
        for (int k = 0; k < STYLE_DIM; ++k)
            acc += sb[k] * (w1a[k * CH + t] * inv);
        g_st1[b * CH + t] = acc + b1a[t];
    } else {
        int c = t - CH;
        float acc = 0.f;
        for (int k = 0; k < STYLE_DIM; ++k)
            acc += sb[k] * (w2a[k * CMID + c] * inv);
        g_st2[b * CMID + c] = acc + b2a[c];
    }
}

// ---------------------------------------------------------------------------
// Demodulation:  d[b,o] = rsqrt( sum_c st[b,c]^2 * sum_tap w[o,c,tap]^2 + 1e-8 )
// ---------------------------------------------------------------------------
__global__ void demod_kernel(const float* __restrict__ w1, const float* __restrict__ w2)
{
    int i = blockIdx.x * 256 + threadIdx.x;
    if (i < BATCH * CMID) {
        int b = i >> 7, o = i & 127;
        float acc = 0.f;
        for (int c = 0; c < CH; ++c) {
            float st = g_st1[b * CH + c];
            float wq = 0.f;
            const float* wp = w1 + ((size_t)o * CH + c) * 9;
            #pragma unroll
            for (int t = 0; t < 9; ++t) { float v = wp[t]; wq += v * v; }
            acc += wq * st * st;
        }
        g_d1[i] = rsqrtf(acc + 1e-8f);
    } else if (i < BATCH * CMID + BATCH * CH) {
        int j = i - BATCH * CMID;
        int b = j >> 5, o = j & 31;
        float acc = 0.f;
        for (int c = 0; c < CMID; ++c) {
            float st = g_st2[b * CMID + c];
            float wq = 0.f;
            const float* wp = w2 + ((size_t)o * CMID + c) * 9;
            #pragma unroll
            for (int t = 0; t < 9; ++t) { float v = wp[t]; wq += v * v; }
            acc += wq * st * st;
        }
        g_d2[j] = rsqrtf(acc + 1e-8f);
    }
}

// ---------------------------------------------------------------------------
// Hash retrieve: gather 4 corners per level, bilinear blend, fold in st1.
// One thread per (b, pixel). Writes g_x in (b, c, p) planes (coalesced STG).
// ---------------------------------------------------------------------------
__global__ void __launch_bounds__(256) retrieve_kernel(
    const float* __restrict__ tables,   // (B, 16, T, 2)
    const float* __restrict__ coords,   // (B, P, 2)
    ResArr R)
{
    int idx = blockIdx.x * 256 + threadIdx.x;
    int b = idx >> 16;
    int p = idx & 65535;

    __shared__ float s1[CH];
    if (threadIdx.x < CH) s1[threadIdx.x] = g_st1[b * CH + threadIdx.x];
    __syncthreads();

    float cx = coords[((size_t)b * NPIX + p) * 2 + 0];
    float cy = coords[((size_t)b * NPIX + p) * 2 + 1];

    #pragma unroll
    for (int l = 0; l < 16; ++l) {
        float rf = (float)R.r[l];
        float px = cx * rf, py = cy * rf;
        float fx0 = floorf(px), fy0 = floorf(py);
        float fx = px - fx0, fy = py - fy0;
        unsigned x0 = (unsigned)fx0, y0 = (unsigned)fy0;
        unsigned hy0 = y0 * PRIME, hy1 = (y0 + 1u) * PRIME;
        unsigned h00 = (x0 ^ hy0) & 65535u;
        unsigned h10 = ((x0 + 1u) ^ hy0) & 65535u;
        unsigned h01 = (x0 ^ hy1) & 65535u;
        unsigned h11 = ((x0 + 1u) ^ hy1) & 65535u;
        const float2* tab = reinterpret_cast<const float2*>(tables) + ((size_t)(b * 16 + l) << 16);
        float2 f00 = __ldg(tab + h00);
        float2 f10 = __ldg(tab + h10);
        float2 f01 = __ldg(tab + h01);
        float2 f11 = __ldg(tab + h11);
        float w00 = (1.f - fx) * (1.f - fy), w10 = fx * (1.f - fy);
        float w01 = (1.f - fx) * fy,         w11 = fx * fy;
        float e0 = w00 * f00.x + w10 * f10.x + w01 * f01.x + w11 * f11.x;
        float e1 = w00 * f00.y + w10 * f10.y + w01 * f01.y + w11 * f11.y;
        g_x[(((size_t)b * CH + 2 * l    ) << 16) + p] = e0 * s1[2 * l];
        g_x[(((size_t)b * CH + 2 * l + 1) << 16) + p] = e1 * s1[2 * l + 1];
    }
}

// ---------------------------------------------------------------------------
// Direct 3x3 conv, SAME padding.
// Tile: 32x32 pixels, 256 threads, 4 px/thread (along x), 16 out channels
// register-blocked, input channels staged in smem in chunks of 16.
// PASS 1: g_x(32ch) -> g_y1(128ch), epilogue: lrelu*sqrt2 * d1 * st2
// PASS 2: g_y1(128ch) -> g_tok(32ch), epilogue: linear, * d2
// ---------------------------------------------------------------------------
template<int PASS>
__global__ void __launch_bounds__(256, 2) conv3x3_kernel(
    const float* __restrict__ wgt, const float* __restrict__ bias)
{
    constexpr int CIN   = (PASS == 1) ? CH   : CMID;
    constexpr int COUT  = (PASS == 1) ? CMID : CH;
    constexpr int CHUNK = 16;
    constexpr int OG    = 16;
    constexpr int XPITCH = 35;                   // 34 cols padded to 35 (bank-safe)
    constexpr int XPLANE = 34 * XPITCH;          // 1190

    const float* xin  = (PASS == 1) ? g_x  : g_y1;
    float*       yout = (PASS == 1) ? g_y1 : g_tok;
    const float* dsc  = (PASS == 1) ? g_d1 : g_d2;

    extern __shared__ float sm[];
    float* xs = sm;                              // [CHUNK][34][35]
    float* ws = sm + CHUNK * XPLANE;             // [OG][CHUNK][9]

    int b  = blockIdx.z;
    int bx = blockIdx.x * 32;
    int by = blockIdx.y * 32;
    int tid = threadIdx.x;
    int tx = (tid & 7) * 4;                      // 0..28
    int ty = tid >> 3;                           // 0..31
    const float* xb = xin + (size_t)b * CIN * NPIX;

    for (int og = 0; og < COUT / OG; ++og) {
        float acc[OG][4];
        #pragma unroll
        for (int o = 0; o < OG; ++o)
            #pragma unroll
            for (int q = 0; q < 4; ++q) acc[o][q] = 0.f;

        for (int c0 = 0; c0 < CIN; c0 += CHUNK) {
            __syncthreads();
            // stage weights for this (og, chunk): layout ws[o][cc][t]
            for (int i = tid; i < OG * CHUNK * 9; i += 256) {
                int o = i / (CHUNK * 9);
                int r = i - o * (CHUNK * 9);
                int cc = r / 9, t = r - cc * 9;
                ws[i] = wgt[(((size_t)(og * OG + o) * CIN) + (c0 + cc)) * 9 + t];
            }
            // stage input tile 34x34 (zero-padded halo)
            for (int i = tid; i < CHUNK * 34 * 34; i += 256) {
                int cc = i / (34 * 34);
                int r = i - cc * (34 * 34);
                int rr = r / 34, col = r - rr * 34;
                int gy = by + rr - 1, gx = bx + col - 1;
                float v = 0.f;
                if ((unsigned)gy < 256u && (unsigned)gx < 256u)
                    v = xb[((size_t)(c0 + cc) << 16) + gy * 256 + gx];
                xs[cc * XPLANE + rr * XPITCH + col] = v;
            }
            __syncthreads();

            for (int cc = 0; cc < CHUNK; ++cc) {
                const float* xr = xs + cc * XPLANE;
                const float* wr = ws + cc * 9;
                #pragma unroll
                for (int kh = 0; kh < 3; ++kh) {
                    const float* row = xr + (ty + kh) * XPITCH + tx;
                    #pragma unroll
                    for (int kw = 0; kw < 3; ++kw) {
                        float x0v = row[kw + 0];
                        float x1v = row[kw + 1];
                        float x2v = row[kw + 2];
                        float x3v = row[kw + 3];
                        int t = kh * 3 + kw;
                        #pragma unroll
                        for (int o = 0; o < OG; ++o) {
                            float wv = wr[o * (CHUNK * 9) + t];
                            acc[o][0] += wv * x0v;
                            acc[o][1] += wv * x1v;
                            acc[o][2] += wv * x2v;
                            acc[o][3] += wv * x3v;
                        }
                    }
                }
            }
        }

        // epilogue
        #pragma unroll
        for (int o = 0; o < OG; ++o) {
            int oc = og * OG + o;
            float d  = dsc[b * COUT + oc];
            float bv = bias[oc];
            float pm = (PASS == 1) ? g_st2[b * CMID + oc] : 1.f;
            size_t obase = ((size_t)b * COUT + oc) * NPIX + (size_t)(by + ty) * 256 + bx;
            #pragma unroll
            for (int q = 0; q < 4; ++q) {
                float y = acc[o][q] * d + bv;
                if (PASS == 1) {
                    y = (y < 0.f ? 0.2f * y : y) * 1.4142135623730951f;
                    y *= pm;
                }
                yout[obase + tx + q] = y;
            }
        }
    }
}

// ---------------------------------------------------------------------------
// Hash recon: scatter-add w * tok into output tables (atomics, no return).
// ---------------------------------------------------------------------------
__global__ void __launch_bounds__(256) recon_kernel(
    const float* __restrict__ coords, float* __restrict__ out, ResArr R)
{
    int idx = blockIdx.x * 256 + threadIdx.x;
    int b = idx >> 16;
    int p = idx & 65535;

    float cx = coords[((size_t)b * NPIX + p) * 2 + 0];
    float cy = coords[((size_t)b * NPIX + p) * 2 + 1];

    float v[CH];
    #pragma unroll
    for (int c = 0; c < CH; ++c)
        v[c] = g_tok[(((size_t)b * CH + c) << 16) + p];

    #pragma unroll
    for (int l = 0; l < 16; ++l) {
        float rf = (float)R.r[l];
        float px = cx * rf, py = cy * rf;
        float fx0 = floorf(px), fy0 = floorf(py);
        float fx = px - fx0, fy = py - fy0;
        unsigned x0 = (unsigned)fx0, y0 = (unsigned)fy0;
        unsigned hy0 = y0 * PRIME, hy1 = (y0 + 1u) * PRIME;
        unsigned h00 = (x0 ^ hy0) & 65535u;
        unsigned h10 = ((x0 + 1u) ^ hy0) & 65535u;
        unsigned h01 = (x0 ^ hy1) & 65535u;
        unsigned h11 = ((x0 + 1u) ^ hy1) & 65535u;
        float w00 = (1.f - fx) * (1.f - fy), w10 = fx * (1.f - fy);
        float w01 = (1.f - fx) * fy,         w11 = fx * fy;
        float a0 = v[2 * l], a1 = v[2 * l + 1];
        float* ob = out + ((size_t)(b * 16 + l) << 17);   // * T * 2
        atomicAdd(ob + 2 * h00,     w00 * a0);
        atomicAdd(ob + 2 * h00 + 1, w00 * a1);
        atomicAdd(ob + 2 * h10,     w10 * a0);
        atomicAdd(ob + 2 * h10 + 1, w10 * a1);
        atomicAdd(ob + 2 * h01,     w01 * a0);
        atomicAdd(ob + 2 * h01 + 1, w01 * a1);
        atomicAdd(ob + 2 * h11,     w11 * a0);
        atomicAdd(ob + 2 * h11 + 1, w11 * a1);
    }
}

// ---------------------------------------------------------------------------
// Launcher
// ---------------------------------------------------------------------------
extern "C" void kernel_launch(void* const* d_in, const int* in_sizes, int n_in,
                              void* d_out, int out_size)
{
    const float* inputs = (const float*)d_in[0];
    const float* s      = (const float*)d_in[1];
    const float* coords = (const float*)d_in[2];
    const float* w1_aff = (const float*)d_in[3];
    const float* b1_aff = (const float*)d_in[4];
    const float* w1     = (const float*)d_in[5];
    const float* b1     = (const float*)d_in[6];
    const float* w2_aff = (const float*)d_in[7];
    const float* b2_aff = (const float*)d_in[8];
    const float* w2     = (const float*)d_in[9];
    const float* b2     = (const float*)d_in[10];
    float* out = (float*)d_out;

    // Level resolutions: same double-precision libm sequence as the reference
    // Python (exp/log/pow/floor) so the l=15 floor boundary bit-matches.
    ResArr R;
    double bb = exp((log(256.0) - log(16.0)) / 15.0);
    for (int l = 0; l < 16; ++l)
        R.r[l] = (int)floor(16.0 * pow(bb, (double)l));

    // 85376 B dynamic smem for the conv kernels
    const int SMEM_BYTES = (16 * 34 * 35 + 16 * 16 * 9) * (int)sizeof(float);
    cudaFuncSetAttribute(conv3x3_kernel<1>, cudaFuncAttributeMaxDynamicSharedMemorySize, SMEM_BYTES);
    cudaFuncSetAttribute(conv3x3_kernel<2>, cudaFuncAttributeMaxDynamicSharedMemorySize, SMEM_BYTES);

    cudaMemsetAsync(d_out, 0, (size_t)out_size * sizeof(float));

    styles_kernel<<<BATCH, CH + CMID>>>(s, w1_aff, b1_aff, w2_aff, b2_aff);
    demod_kernel<<<5, 256>>>(w1, w2);

    retrieve_kernel<<<(BATCH * NPIX) / 256, 256>>>(inputs, coords, R);

    dim3 cgrid(8, 8, BATCH);
    conv3x3_kernel<1><<<cgrid, 256, SMEM_BYTES>>>(w1, b1);
    conv3x3_kernel<2><<<cgrid, 256, SMEM_BYTES>>>(w2, b2);

    recon_kernel<<<(BATCH * NPIX) / 256, 256>>>(coords, out, R);
}

// round 2
// speedup vs baseline: 1.1780x; 1.1780x over previous
#include <cuda_runtime.h>
#include <math.h>

// ---------------------------------------------------------------------------
// Problem constants
// ---------------------------------------------------------------------------
#define TABLE_NUM 16
#define STYLE_DIM 512
#define SAMPLE_RES 256
#define CH 32              // TABLE_NUM * 2
#define CMID 128           // CH * 4
#define TABLE_DIM 65536
#define BATCH 8
#define NPIX 65536         // 256*256
#define PRIME 2654435761u

typedef unsigned long long u64;

// ---------------------------------------------------------------------------
// Scratch (device globals; no runtime allocation allowed)
// ---------------------------------------------------------------------------
__device__ float g_x  [(size_t)BATCH * CH   * NPIX];  // modulated conv1 input (b,c,p)
__device__ float g_y1 [(size_t)BATCH * CMID * NPIX];  // conv1 out * st2 (b,c,p)
__device__ float g_tok[(size_t)BATCH * CH   * NPIX];  // conv2 out (b,c,p)
__device__ float g_st1[BATCH * CH];
__device__ float g_st2[BATCH * CMID];
__device__ float g_d1 [BATCH * CMID];
__device__ float g_d2 [BATCH * CH];

struct ResArr { int r[16]; };

// ---------------------------------------------------------------------------
// f32x2 packed-math helpers (Blackwell packed FP32 pipe)
// ---------------------------------------------------------------------------
__device__ __forceinline__ void ffma2(u64& acc, u64 a, u64 b) {
    asm("fma.rn.f32x2 %0, %1, %2, %0;" : "+l"(acc) : "l"(a), "l"(b));
}
__device__ __forceinline__ u64 bc2(float x) {
    u64 r;
    asm("mov.b64 %0, {%1, %1};" : "=l"(r) : "r"(__float_as_uint(x)));
    return r;
}
__device__ __forceinline__ void unpack2(u64 v, float& lo, float& hi) {
    unsigned a, b;
    asm("mov.b64 {%0, %1}, %2;" : "=r"(a), "=r"(b) : "l"(v));
    lo = __uint_as_float(a);
    hi = __uint_as_float(b);
}

// ---------------------------------------------------------------------------
// Styles:   st = s @ (w_aff / sqrt(512)) + b_aff
// ---------------------------------------------------------------------------
__global__ void styles_kernel(const float* __restrict__ s,
                              const float* __restrict__ w1a, const float* __restrict__ b1a,
                              const float* __restrict__ w2a, const float* __restrict__ b2a)
{
    int b = blockIdx.x;
    int t = threadIdx.x;
    float inv = 1.0f / sqrtf(512.0f);
    const float* sb = s + b * STYLE_DIM;
    if (t < CH) {
        float acc = 0.f;
        for (int k = 0; k < STYLE_DIM; ++k)
            acc += sb[k] * (w1a[k * CH + t] * inv);
        g_st1[b * CH + t] = acc + b1a[t];
    } else {
        int c = t - CH;
        float acc = 0.f;
        for (int k = 0; k < STYLE_DIM; ++k)
            acc += sb[k] * (w2a[k * CMID + c] * inv);
        g_st2[b * CMID + c] = acc + b2a[c];
    }
}

// ---------------------------------------------------------------------------
// Demodulation:  d[b,o] = rsqrt( sum_c st[b,c]^2 * sum_tap w[o,c,tap]^2 + 1e-8 )
// ---------------------------------------------------------------------------
__global__ void demod_kernel(const float* __restrict__ w1, const float* __restrict__ w2)
{
    int i = blockIdx.x * 256 + threadIdx.x;
    if (i < BATCH * CMID) {
        int b = i >> 7, o = i & 127;
        float acc = 0.f;
        for (int c = 0; c < CH; ++c) {
            float st = g_st1[b * CH + c];
            float wq = 0.f;
            const float* wp = w1 + ((size_t)o * CH + c) * 9;
            #pragma unroll
            for (int t = 0; t < 9; ++t) { float v = wp[t]; wq += v * v; }
            acc += wq * st * st;
        }
        g_d1[i] = rsqrtf(acc + 1e-8f);
    } else if (i < BATCH * CMID + BATCH * CH) {
        int j = i - BATCH * CMID;
        int b = j >> 5, o = j & 31;
        float acc = 0.f;
        for (int c = 0; c < CMID; ++c) {
            float st = g_st2[b * CMID + c];
            float wq = 0.f;
            const float* wp = w2 + ((size_t)o * CMID + c) * 9;
            #pragma unroll
            for (int t = 0; t < 9; ++t) { float v = wp[t]; wq += v * v; }
            acc += wq * st * st;
        }
        g_d2[j] = rsqrtf(acc + 1e-8f);
    }
}

// ---------------------------------------------------------------------------
// Hash retrieve: gather 4 corners per level, bilinear blend, fold in st1.
// ---------------------------------------------------------------------------
__global__ void __launch_bounds__(256) retrieve_kernel(
    const float* __restrict__ tables,   // (B, 16, T, 2)
    const float* __restrict__ coords,   // (B, P, 2)
    ResArr R)
{
    int idx = blockIdx.x * 256 + threadIdx.x;
    int b = idx >> 16;
    int p = idx & 65535;

    __shared__ float s1[CH];
    if (threadIdx.x < CH) s1[threadIdx.x] = g_st1[b * CH + threadIdx.x];
    __syncthreads();

    float cx = coords[((size_t)b * NPIX + p) * 2 + 0];
    float cy = coords[((size_t)b * NPIX + p) * 2 + 1];

    #pragma unroll
    for (int l = 0; l < 16; ++l) {
        float rf = (float)R.r[l];
        float px = cx * rf, py = cy * rf;
        float fx0 = floorf(px), fy0 = floorf(py);
        float fx = px - fx0, fy = py - fy0;
        unsigned x0 = (unsigned)fx0, y0 = (unsigned)fy0;
        unsigned hy0 = y0 * PRIME, hy1 = (y0 + 1u) * PRIME;
        unsigned h00 = (x0 ^ hy0) & 65535u;
        unsigned h10 = ((x0 + 1u) ^ hy0) & 65535u;
        unsigned h01 = (x0 ^ hy1) & 65535u;
        unsigned h11 = ((x0 + 1u) ^ hy1) & 65535u;
        const float2* tab = reinterpret_cast<const float2*>(tables) + ((size_t)(b * 16 + l) << 16);
        float2 f00 = __ldg(tab + h00);
        float2 f10 = __ldg(tab + h10);
        float2 f01 = __ldg(tab + h01);
        float2 f11 = __ldg(tab + h11);
        float w00 = (1.f - fx) * (1.f - fy), w10 = fx * (1.f - fy);
        float w01 = (1.f - fx) * fy,         w11 = fx * fy;
        float e0 = w00 * f00.x + w10 * f10.x + w01 * f01.x + w11 * f11.x;
        float e1 = w00 * f00.y + w10 * f10.y + w01 * f01.y + w11 * f11.y;
        g_x[(((size_t)b * CH + 2 * l    ) << 16) + p] = e0 * s1[2 * l];
        g_x[(((size_t)b * CH + 2 * l + 1) << 16) + p] = e1 * s1[2 * l + 1];
    }
}

// ---------------------------------------------------------------------------
// Direct 3x3 conv, SAME padding, packed f32x2 math.
// Tile: 32x32 pixels, 256 threads, 4 px/thread (along x).
// 16 out channels register-blocked as 8 packed PAIRS:
//    acc[op][q] = (acc for oc=2*op, acc for oc=2*op+1) at pixel q.
// FFMA2: d=(acc_o,acc_o1) += (w_o,w_o1) * (x,x).
// Weights staged in smem as [cc][tap][o] so an o-pair is one aligned LDS.64.
// PASS 1: g_x(32ch) -> g_y1(128ch), epilogue: lrelu*sqrt2 * d1 * st2
// PASS 2: g_y1(128ch) -> g_tok(32ch), epilogue: linear, * d2
// ---------------------------------------------------------------------------
template<int PASS>
__global__ void __launch_bounds__(256, 2) conv3x3_kernel(
    const float* __restrict__ wgt, const float* __restrict__ bias)
{
    constexpr int CIN   = (PASS == 1) ? CH   : CMID;
    constexpr int COUT  = (PASS == 1) ? CMID : CH;
    constexpr int CHUNK = 16;
    constexpr int OG    = 16;                    // out channels per og pass
    constexpr int XPITCH = 35;                   // 34 cols padded to 35 (bank-safe)
    constexpr int XPLANE = 34 * XPITCH;          // 1190

    const float* xin  = (PASS == 1) ? g_x  : g_y1;
    float*       yout = (PASS == 1) ? g_y1 : g_tok;
    const float* dsc  = (PASS == 1) ? g_d1 : g_d2;

    extern __shared__ float sm[];
    float* xs = sm;                              // [CHUNK][34][35]
    float* ws = sm + CHUNK * XPLANE;             // [CHUNK][9][OG]

    int b  = blockIdx.z;
    int bx = blockIdx.x * 32;
    int by = blockIdx.y * 32;
    int tid = threadIdx.x;
    int tx = (tid & 7) * 4;                      // 0..28
    int ty = tid >> 3;                           // 0..31
    const float* xb = xin + (size_t)b * CIN * NPIX;

    #pragma unroll 1
    for (int og = 0; og < COUT / OG; ++og) {
        u64 acc[OG / 2][4];
        #pragma unroll
        for (int o = 0; o < OG / 2; ++o)
            #pragma unroll
            for (int q = 0; q < 4; ++q) acc[o][q] = 0ull;

        #pragma unroll 1
        for (int c0 = 0; c0 < CIN; c0 += CHUNK) {
            __syncthreads();
            // stage weights: ws[cc][t][o] (o-pairs contiguous for LDS.64)
            for (int i = tid; i < CHUNK * 9 * OG; i += 256) {
                int cc = i / (9 * OG);
                int r  = i - cc * (9 * OG);
                int t  = r / OG, o = r - t * OG;
                ws[i] = wgt[(((size_t)(og * OG + o) * CIN) + (c0 + cc)) * 9 + t];
            }
            // stage input tile 34x34 (zero-padded halo)
            for (int i = tid; i < CHUNK * 34 * 34; i += 256) {
                int cc = i / (34 * 34);
                int r = i - cc * (34 * 34);
                int rr = r / 34, col = r - rr * 34;
                int gy = by + rr - 1, gx = bx + col - 1;
                float v = 0.f;
                if ((unsigned)gy < 256u && (unsigned)gx < 256u)
                    v = xb[((size_t)(c0 + cc) << 16) + gy * 256 + gx];
                xs[cc * XPLANE + rr * XPITCH + col] = v;
            }
            __syncthreads();

            #pragma unroll 1
            for (int cc = 0; cc < CHUNK; ++cc) {
                const float* xr = xs + cc * XPLANE + ty * XPITCH + tx;
                const float* wb = ws + cc * (9 * OG);
                #pragma unroll
                for (int kh = 0; kh < 3; ++kh) {
                    const float* row = xr + kh * XPITCH;
                    // 6-wide window covers kw+q for kw 0..2, q 0..3
                    u64 bcv[6];
                    #pragma unroll
                    for (int j = 0; j < 6; ++j) bcv[j] = bc2(row[j]);
                    #pragma unroll
                    for (int kw = 0; kw < 3; ++kw) {
                        const u64* wp = reinterpret_cast<const u64*>(wb + (kh * 3 + kw) * OG);
                        #pragma unroll
                        for (int op = 0; op < OG / 2; ++op) {
                            u64 wv = wp[op];
                            ffma2(acc[op][0], wv, bcv[kw + 0]);
                            ffma2(acc[op][1], wv, bcv[kw + 1]);
                            ffma2(acc[op][2], wv, bcv[kw + 2]);
                            ffma2(acc[op][3], wv, bcv[kw + 3]);
                        }
                    }
                }
            }
        }

        // epilogue
        #pragma unroll
        for (int op = 0; op < OG / 2; ++op) {
            float y0[4], y1[4];
            #pragma unroll
            for (int q = 0; q < 4; ++q) unpack2(acc[op][q], y0[q], y1[q]);
            #pragma unroll
            for (int h = 0; h < 2; ++h) {
                int oc = og * OG + 2 * op + h;
                float d  = dsc[b * COUT + oc];
                float bv = bias[oc];
                float pm = (PASS == 1) ? g_st2[b * CMID + oc] : 1.f;
                float* yp = (h == 0) ? y0 : y1;
                float4 v;
                float r0, r1, r2, r3;
                r0 = yp[0] * d + bv; r1 = yp[1] * d + bv;
                r2 = yp[2] * d + bv; r3 = yp[3] * d + bv;
                if (PASS == 1) {
                    r0 = (r0 < 0.f ? 0.2f * r0 : r0) * 1.4142135623730951f * pm;
                    r1 = (r1 < 0.f ? 0.2f * r1 : r1) * 1.4142135623730951f * pm;
                    r2 = (r2 < 0.f ? 0.2f * r2 : r2) * 1.4142135623730951f * pm;
                    r3 = (r3 < 0.f ? 0.2f * r3 : r3) * 1.4142135623730951f * pm;
                }
                v.x = r0; v.y = r1; v.z = r2; v.w = r3;
                size_t obase = ((size_t)b * COUT + oc) * NPIX + (size_t)(by + ty) * 256 + bx + tx;
                *reinterpret_cast<float4*>(yout + obase) = v;
            }
        }
    }
}

// ---------------------------------------------------------------------------
// Hash recon: scatter-add w * tok into output tables (atomics, no return).
// ---------------------------------------------------------------------------
__global__ void __launch_bounds__(256) recon_kernel(
    const float* __restrict__ coords, float* __restrict__ out, ResArr R)
{
    int idx = blockIdx.x * 256 + threadIdx.x;
    int b = idx >> 16;
    int p = idx & 65535;

    float cx = coords[((size_t)b * NPIX + p) * 2 + 0];
    float cy = coords[((size_t)b * NPIX + p) * 2 + 1];

    float v[CH];
    #pragma unroll
    for (int c = 0; c < CH; ++c)
        v[c] = g_tok[(((size_t)b * CH + c) << 16) + p];

    #pragma unroll
    for (int l = 0; l < 16; ++l) {
        float rf = (float)R.r[l];
        float px = cx * rf, py = cy * rf;
        float fx0 = floorf(px), fy0 = floorf(py);
        float fx = px - fx0, fy = py - fy0;
        unsigned x0 = (unsigned)fx0, y0 = (unsigned)fy0;
        unsigned hy0 = y0 * PRIME, hy1 = (y0 + 1u) * PRIME;
        unsigned h00 = (x0 ^ hy0) & 65535u;
        unsigned h10 = ((x0 + 1u) ^ hy0) & 65535u;
        unsigned h01 = (x0 ^ hy1) & 65535u;
        unsigned h11 = ((x0 + 1u) ^ hy1) & 65535u;
        float w00 = (1.f - fx) * (1.f - fy), w10 = fx * (1.f - fy);
        float w01 = (1.f - fx) * fy,         w11 = fx * fy;
        float a0 = v[2 * l], a1 = v[2 * l + 1];
        float* ob = out + ((size_t)(b * 16 + l) << 17);   // * T * 2
        atomicAdd(ob + 2 * h00,     w00 * a0);
        atomicAdd(ob + 2 * h00 + 1, w00 * a1);
        atomicAdd(ob + 2 * h10,     w10 * a0);
        atomicAdd(ob + 2 * h10 + 1, w10 * a1);
        atomicAdd(ob + 2 * h01,     w01 * a0);
        atomicAdd(ob + 2 * h01 + 1, w01 * a1);
        atomicAdd(ob + 2 * h11,     w11 * a0);
        atomicAdd(ob + 2 * h11 + 1, w11 * a1);
    }
}

// ---------------------------------------------------------------------------
// Launcher
// ---------------------------------------------------------------------------
extern "C" void kernel_launch(void* const* d_in, const int* in_sizes, int n_in,
                              void* d_out, int out_size)
{
    const float* inputs = (const float*)d_in[0];
    const float* s      = (const float*)d_in[1];
    const float* coords = (const float*)d_in[2];
    const float* w1_aff = (const float*)d_in[3];
    const float* b1_aff = (const float*)d_in[4];
    const float* w1     = (const float*)d_in[5];
    const float* b1     = (const float*)d_in[6];
    const float* w2_aff = (const float*)d_in[7];
    const float* b2_aff = (const float*)d_in[8];
    const float* w2     = (const float*)d_in[9];
    const float* b2     = (const float*)d_in[10];
    float* out = (float*)d_out;

    // Level resolutions: same double-precision libm sequence as the reference.
    ResArr R;
    double bb = exp((log(256.0) - log(16.0)) / 15.0);
    for (int l = 0; l < 16; ++l)
        R.r[l] = (int)floor(16.0 * pow(bb, (double)l));

    const int SMEM_BYTES = (16 * 34 * 35 + 16 * 9 * 16) * (int)sizeof(float);
    cudaFuncSetAttribute(conv3x3_kernel<1>, cudaFuncAttributeMaxDynamicSharedMemorySize, SMEM_BYTES);
    cudaFuncSetAttribute(conv3x3_kernel<2>, cudaFuncAttributeMaxDynamicSharedMemorySize, SMEM_BYTES);

    cudaMemsetAsync(d_out, 0, (size_t)out_size * sizeof(float));

    styles_kernel<<<BATCH, CH + CMID>>>(s, w1_aff, b1_aff, w2_aff, b2_aff);
    demod_kernel<<<5, 256>>>(w1, w2);

    retrieve_kernel<<<(BATCH * NPIX) / 256, 256>>>(inputs, coords, R);

    dim3 cgrid(8, 8, BATCH);
    conv3x3_kernel<1><<<cgrid, 256, SMEM_BYTES>>>(w1, b1);
    conv3x3_kernel<2><<<cgrid, 256, SMEM_BYTES>>>(w2, b2);

    recon_kernel<<<(BATCH * NPIX) / 256, 256>>>(coords, out, R);
}

// round 3
// speedup vs baseline: 1.3237x; 1.1237x over previous
#include <cuda_runtime.h>
#include <math.h>

// ---------------------------------------------------------------------------
// Problem constants
// ---------------------------------------------------------------------------
#define TABLE_NUM 16
#define STYLE_DIM 512
#define SAMPLE_RES 256
#define CH 32              // TABLE_NUM * 2
#define CMID 128           // CH * 4
#define TABLE_DIM 65536
#define BATCH 8
#define NPIX 65536         // 256*256
#define PRIME 2654435761u

typedef unsigned long long u64;

// ---------------------------------------------------------------------------
// Scratch (device globals; no runtime allocation allowed)
// ---------------------------------------------------------------------------
__device__ float g_x  [(size_t)BATCH * CH   * NPIX];  // modulated conv1 input (b,c,p)
__device__ float g_y1 [(size_t)BATCH * CMID * NPIX];  // conv1 out * st2 (b,c,p)
__device__ float g_tok[(size_t)BATCH * CH   * NPIX];  // conv2 out (b,c,p)
__device__ float g_st1[BATCH * CH];
__device__ float g_st2[BATCH * CMID];
__device__ float g_d1 [BATCH * CMID];
__device__ float g_d2 [BATCH * CH];

struct ResArr { int r[16]; };

// ---------------------------------------------------------------------------
// f32x2 packed-math helpers (Blackwell packed FP32 pipe)
// ---------------------------------------------------------------------------
__device__ __forceinline__ void ffma2(u64& acc, u64 a, u64 b) {
    asm("fma.rn.f32x2 %0, %1, %2, %0;" : "+l"(acc) : "l"(a), "l"(b));
}
__device__ __forceinline__ u64 pack2(float x) {
    u64 r;
    asm("mov.b64 %0, {%1, %1};" : "=l"(r) : "r"(__float_as_uint(x)));
    return r;
}
__device__ __forceinline__ void unpack2(u64 v, float& lo, float& hi) {
    unsigned a, b;
    asm("mov.b64 {%0, %1}, %2;" : "=r"(a), "=r"(b) : "l"(v));
    lo = __uint_as_float(a);
    hi = __uint_as_float(b);
}

// ---------------------------------------------------------------------------
// Styles:   st = s @ (w_aff / sqrt(512)) + b_aff
// ---------------------------------------------------------------------------
__global__ void styles_kernel(const float* __restrict__ s,
                              const float* __restrict__ w1a, const float* __restrict__ b1a,
                              const float* __restrict__ w2a, const float* __restrict__ b2a)
{
    int b = blockIdx.x;
    int t = threadIdx.x;
    float inv = 1.0f / sqrtf(512.0f);
    const float* sb = s + b * STYLE_DIM;
    if (t < CH) {
        float acc = 0.f;
        for (int k = 0; k < STYLE_DIM; ++k)
            acc += sb[k] * (w1a[k * CH + t] * inv);
        g_st1[b * CH + t] = acc + b1a[t];
    } else {
        int c = t - CH;
        float acc = 0.f;
        for (int k = 0; k < STYLE_DIM; ++k)
            acc += sb[k] * (w2a[k * CMID + c] * inv);
        g_st2[b * CMID + c] = acc + b2a[c];
    }
}

// ---------------------------------------------------------------------------
// Demodulation:  d[b,o] = rsqrt( sum_c st[b,c]^2 * sum_tap w[o,c,tap]^2 + 1e-8 )
// ---------------------------------------------------------------------------
__global__ void demod_kernel(const float* __restrict__ w1, const float* __restrict__ w2)
{
    int i = blockIdx.x * 256 + threadIdx.x;
    if (i < BATCH * CMID) {
        int b = i >> 7, o = i & 127;
        float acc = 0.f;
        for (int c = 0; c < CH; ++c) {
            float st = g_st1[b * CH + c];
            float wq = 0.f;
            const float* wp = w1 + ((size_t)o * CH + c) * 9;
            #pragma unroll
            for (int t = 0; t < 9; ++t) { float v = wp[t]; wq += v * v; }
            acc += wq * st * st;
        }
        g_d1[i] = rsqrtf(acc + 1e-8f);
    } else if (i < BATCH * CMID + BATCH * CH) {
        int j = i - BATCH * CMID;
        int b = j >> 5, o = j & 31;
        float acc = 0.f;
        for (int c = 0; c < CMID; ++c) {
            float st = g_st2[b * CMID + c];
            float wq = 0.f;
            const float* wp = w2 + ((size_t)o * CMID + c) * 9;
            #pragma unroll
            for (int t = 0; t < 9; ++t) { float v = wp[t]; wq += v * v; }
            acc += wq * st * st;
        }
        g_d2[j] = rsqrtf(acc + 1e-8f);
    }
}

// ---------------------------------------------------------------------------
// Hash retrieve: gather 4 corners per level, bilinear blend, fold in st1.
// ---------------------------------------------------------------------------
__global__ void __launch_bounds__(256) retrieve_kernel(
    const float* __restrict__ tables,   // (B, 16, T, 2)
    const float* __restrict__ coords,   // (B, P, 2)
    ResArr R)
{
    int idx = blockIdx.x * 256 + threadIdx.x;
    int b = idx >> 16;
    int p = idx & 65535;

    __shared__ float s1[CH];
    if (threadIdx.x < CH) s1[threadIdx.x] = g_st1[b * CH + threadIdx.x];
    __syncthreads();

    float cx = coords[((size_t)b * NPIX + p) * 2 + 0];
    float cy = coords[((size_t)b * NPIX + p) * 2 + 1];

    #pragma unroll
    for (int l = 0; l < 16; ++l) {
        float rf = (float)R.r[l];
        float px = cx * rf, py = cy * rf;
        float fx0 = floorf(px), fy0 = floorf(py);
        float fx = px - fx0, fy = py - fy0;
        unsigned x0 = (unsigned)fx0, y0 = (unsigned)fy0;
        unsigned hy0 = y0 * PRIME, hy1 = (y0 + 1u) * PRIME;
        unsigned h00 = (x0 ^ hy0) & 65535u;
        unsigned h10 = ((x0 + 1u) ^ hy0) & 65535u;
        unsigned h01 = (x0 ^ hy1) & 65535u;
        unsigned h11 = ((x0 + 1u) ^ hy1) & 65535u;
        const float2* tab = reinterpret_cast<const float2*>(tables) + ((size_t)(b * 16 + l) << 16);
        float2 f00 = __ldg(tab + h00);
        float2 f10 = __ldg(tab + h10);
        float2 f01 = __ldg(tab + h01);
        float2 f11 = __ldg(tab + h11);
        float w00 = (1.f - fx) * (1.f - fy), w10 = fx * (1.f - fy);
        float w01 = (1.f - fx) * fy,         w11 = fx * fy;
        float e0 = w00 * f00.x + w10 * f10.x + w01 * f01.x + w11 * f11.x;
        float e1 = w00 * f00.y + w10 * f10.y + w01 * f01.y + w11 * f11.y;
        g_x[(((size_t)b * CH + 2 * l    ) << 16) + p] = e0 * s1[2 * l];
        g_x[(((size_t)b * CH + 2 * l + 1) << 16) + p] = e1 * s1[2 * l + 1];
    }
}

// ---------------------------------------------------------------------------
// Direct 3x3 conv, SAME padding, packed f32x2 math.
// Grid: (8, 8, B * COUT/OG) — one out-channel group per block (no og loop).
// Tile: 32x32 pixels, 256 threads, 4 px/thread (along x).
// 16 out channels register-blocked as 8 packed pairs.
// x staged DUPLICATED in smem: value v stored as the 64-bit pair (v,v), so the
// FFMA2 broadcast operand is a single aligned LDS.64 (no mov.b64 packing).
// Row pitch 70 floats -> conflict-free for the 4row x 8col warp footprint.
// PASS 1: g_x(32ch) -> g_y1(128ch), epilogue: lrelu*sqrt2 * d1 * st2
// PASS 2: g_y1(128ch) -> g_tok(32ch), epilogue: linear, * d2
// ---------------------------------------------------------------------------
template<int PASS>
__global__ void __launch_bounds__(256, 2) conv3x3_kernel(
    const float* __restrict__ wgt, const float* __restrict__ bias)
{
    constexpr int CIN   = (PASS == 1) ? CH   : CMID;
    constexpr int COUT  = (PASS == 1) ? CMID : CH;
    constexpr int CHUNK = 8;
    constexpr int OG    = 16;                    // out channels per block
    constexpr int XPITCH = 70;                   // 34 duplicated pairs + pad
    constexpr int XPLANE = 34 * XPITCH;          // 2380 floats per channel

    const float* xin  = (PASS == 1) ? g_x  : g_y1;
    float*       yout = (PASS == 1) ? g_y1 : g_tok;
    const float* dsc  = (PASS == 1) ? g_d1 : g_d2;

    extern __shared__ float sm[];
    float* xs = sm;                              // [CHUNK][34][70] duplicated pairs
    float* ws = sm + CHUNK * XPLANE;             // [CHUNK][9][OG]

    int zz = blockIdx.z;
    int b  = zz / (COUT / OG);
    int og = zz - b * (COUT / OG);
    int bx = blockIdx.x * 32;
    int by = blockIdx.y * 32;
    int tid = threadIdx.x;
    int tx = (tid & 7) * 4;                      // 0..28
    int ty = tid >> 3;                           // 0..31
    const float* xb = xin + (size_t)b * CIN * NPIX;

    u64 acc[OG / 2][4];
    #pragma unroll
    for (int o = 0; o < OG / 2; ++o)
        #pragma unroll
        for (int q = 0; q < 4; ++q) acc[o][q] = 0ull;

    #pragma unroll 1
    for (int c0 = 0; c0 < CIN; c0 += CHUNK) {
        __syncthreads();
        // stage weights: ws[cc][t][o] (o-pairs contiguous for LDS.64)
        for (int i = tid; i < CHUNK * 9 * OG; i += 256) {
            int cc = i / (9 * OG);
            int r  = i - cc * (9 * OG);
            int t  = r / OG, o = r - t * OG;
            ws[i] = wgt[(((size_t)(og * OG + o) * CIN) + (c0 + cc)) * 9 + t];
        }
        // stage input tile 34x34, duplicated: (v,v) 64-bit pair per element
        for (int i = tid; i < CHUNK * 34 * 34; i += 256) {
            int cc = i / (34 * 34);
            int r = i - cc * (34 * 34);
            int rr = r / 34, col = r - rr * 34;
            int gy = by + rr - 1, gx = bx + col - 1;
            float v = 0.f;
            if ((unsigned)gy < 256u && (unsigned)gx < 256u)
                v = xb[((size_t)(c0 + cc) << 16) + gy * 256 + gx];
            *reinterpret_cast<u64*>(xs + cc * XPLANE + rr * XPITCH + 2 * col) = pack2(v);
        }
        __syncthreads();

        #pragma unroll 1
        for (int cc = 0; cc < CHUNK; ++cc) {
            const float* xr = xs + cc * XPLANE + ty * XPITCH + 2 * tx;
            const float* wb = ws + cc * (9 * OG);
            #pragma unroll
            for (int kh = 0; kh < 3; ++kh) {
                const u64* row = reinterpret_cast<const u64*>(xr + kh * XPITCH);
                u64 xv[6];
                #pragma unroll
                for (int j = 0; j < 6; ++j) xv[j] = row[j];
                #pragma unroll
                for (int kw = 0; kw < 3; ++kw) {
                    const u64* wp = reinterpret_cast<const u64*>(wb + (kh * 3 + kw) * OG);
                    #pragma unroll
                    for (int op = 0; op < OG / 2; ++op) {
                        u64 wv = wp[op];
                        ffma2(acc[op][0], wv, xv[kw + 0]);
                        ffma2(acc[op][1], wv, xv[kw + 1]);
                        ffma2(acc[op][2], wv, xv[kw + 2]);
                        ffma2(acc[op][3], wv, xv[kw + 3]);
                    }
                }
            }
        }
    }

    // epilogue
    #pragma unroll
    for (int op = 0; op < OG / 2; ++op) {
        float y0[4], y1[4];
        #pragma unroll
        for (int q = 0; q < 4; ++q) unpack2(acc[op][q], y0[q], y1[q]);
        #pragma unroll
        for (int h = 0; h < 2; ++h) {
            int oc = og * OG + 2 * op + h;
            float d  = dsc[b * COUT + oc];
            float bv = bias[oc];
            float pm = (PASS == 1) ? g_st2[b * CMID + oc] : 1.f;
            float* yp = (h == 0) ? y0 : y1;
            float r0 = yp[0] * d + bv, r1 = yp[1] * d + bv;
            float r2 = yp[2] * d + bv, r3 = yp[3] * d + bv;
            if (PASS == 1) {
                r0 = (r0 < 0.f ? 0.2f * r0 : r0) * 1.4142135623730951f * pm;
                r1 = (r1 < 0.f ? 0.2f * r1 : r1) * 1.4142135623730951f * pm;
                r2 = (r2 < 0.f ? 0.2f * r2 : r2) * 1.4142135623730951f * pm;
                r3 = (r3 < 0.f ? 0.2f * r3 : r3) * 1.4142135623730951f * pm;
            }
            float4 v; v.x = r0; v.y = r1; v.z = r2; v.w = r3;
            size_t obase = ((size_t)b * COUT + oc) * NPIX + (size_t)(by + ty) * 256 + bx + tx;
            *reinterpret_cast<float4*>(yout + obase) = v;
        }
    }
}

// ---------------------------------------------------------------------------
// Hash recon: scatter-add w * tok into output tables.
// Uses vectored no-return reductions (red.global.add.v2.f32) — 4 per level.
// ---------------------------------------------------------------------------
__device__ __forceinline__ void red2(float* p, float a, float b) {
    asm volatile("red.global.add.v2.f32 [%0], {%1, %2};"
                 :: "l"(p), "f"(a), "f"(b) : "memory");
}

__global__ void __launch_bounds__(256) recon_kernel(
    const float* __restrict__ coords, float* __restrict__ out, ResArr R)
{
    int idx = blockIdx.x * 256 + threadIdx.x;
    int b = idx >> 16;
    int p = idx & 65535;

    float cx = coords[((size_t)b * NPIX + p) * 2 + 0];
    float cy = coords[((size_t)b * NPIX + p) * 2 + 1];

    float v[CH];
    #pragma unroll
    for (int c = 0; c < CH; ++c)
        v[c] = g_tok[(((size_t)b * CH + c) << 16) + p];

    #pragma unroll
    for (int l = 0; l < 16; ++l) {
        float rf = (float)R.r[l];
        float px = cx * rf, py = cy * rf;
        float fx0 = floorf(px), fy0 = floorf(py);
        float fx = px - fx0, fy = py - fy0;
        unsigned x0 = (unsigned)fx0, y0 = (unsigned)fy0;
        unsigned hy0 = y0 * PRIME, hy1 = (y0 + 1u) * PRIME;
        unsigned h00 = (x0 ^ hy0) & 65535u;
        unsigned h10 = ((x0 + 1u) ^ hy0) & 65535u;
        unsigned h01 = (x0 ^ hy1) & 65535u;
        unsigned h11 = ((x0 + 1u) ^ hy1) & 65535u;
        float w00 = (1.f - fx) * (1.f - fy), w10 = fx * (1.f - fy);
        float w01 = (1.f - fx) * fy,         w11 = fx * fy;
        float a0 = v[2 * l], a1 = v[2 * l + 1];
        float* ob = out + ((size_t)(b * 16 + l) << 17);   // * T * 2
        red2(ob + 2 * h00, w00 * a0, w00 * a1);
        red2(ob + 2 * h10, w10 * a0, w10 * a1);
        red2(ob + 2 * h01, w01 * a0, w01 * a1);
        red2(ob + 2 * h11, w11 * a0, w11 * a1);
    }
}

// ---------------------------------------------------------------------------
// Launcher
// ---------------------------------------------------------------------------
extern "C" void kernel_launch(void* const* d_in, const int* in_sizes, int n_in,
                              void* d_out, int out_size)
{
    const float* inputs = (const float*)d_in[0];
    const float* s      = (const float*)d_in[1];
    const float* coords = (const float*)d_in[2];
    const float* w1_aff = (const float*)d_in[3];
    const float* b1_aff = (const float*)d_in[4];
    const float* w1     = (const float*)d_in[5];
    const float* b1     = (const float*)d_in[6];
    const float* w2_aff = (const float*)d_in[7];
    const float* b2_aff = (const float*)d_in[8];
    const float* w2     = (const float*)d_in[9];
    const float* b2     = (const float*)d_in[10];
    float* out = (float*)d_out;

    // Level resolutions: same double-precision libm sequence as the reference.
    ResArr R;
    double bb = exp((log(256.0) - log(16.0)) / 15.0);
    for (int l = 0; l < 16; ++l)
        R.r[l] = (int)floor(16.0 * pow(bb, (double)l));

    const int SMEM_BYTES = (8 * 34 * 70 + 8 * 9 * 16) * (int)sizeof(float); // 80768 B
    cudaFuncSetAttribute(conv3x3_kernel<1>, cudaFuncAttributeMaxDynamicSharedMemorySize, SMEM_BYTES);
    cudaFuncSetAttribute(conv3x3_kernel<2>, cudaFuncAttributeMaxDynamicSharedMemorySize, SMEM_BYTES);

    cudaMemsetAsync(d_out, 0, (size_t)out_size * sizeof(float));

    styles_kernel<<<BATCH, CH + CMID>>>(s, w1_aff, b1_aff, w2_aff, b2_aff);
    demod_kernel<<<5, 256>>>(w1, w2);

    retrieve_kernel<<<(BATCH * NPIX) / 256, 256>>>(inputs, coords, R);

    dim3 cgrid1(8, 8, BATCH * (CMID / 16));
    conv3x3_kernel<1><<<cgrid1, 256, SMEM_BYTES>>>(w1, b1);
    dim3 cgrid2(8, 8, BATCH * (CH / 16));
    conv3x3_kernel<2><<<cgrid2, 256, SMEM_BYTES>>>(w2, b2);

    recon_kernel<<<(BATCH * NPIX) / 256, 256>>>(coords, out, R);
}

// round 5
// speedup vs baseline: 1.3368x; 1.0098x over previous
#include <cuda_runtime.h>
#include <math.h>

// ---------------------------------------------------------------------------
// Problem constants
// ---------------------------------------------------------------------------
#define TABLE_NUM 16
#define STYLE_DIM 512
#define SAMPLE_RES 256
#define CH 32              // TABLE_NUM * 2
#define CMID 128           // CH * 4
#define TABLE_DIM 65536
#define BATCH 8
#define NPIX 65536         // 256*256
#define PRIME 2654435761u

typedef unsigned long long u64;

// ---------------------------------------------------------------------------
// Scratch (device globals; no runtime allocation allowed)
// ---------------------------------------------------------------------------
__device__ float g_x  [(size_t)BATCH * CH   * NPIX];  // modulated conv1 input (b,c,p)
__device__ float g_y1 [(size_t)BATCH * CMID * NPIX];  // conv1 out * st2 (b,c,p)
__device__ float g_tok[(size_t)BATCH * CH   * NPIX];  // conv2 out (b,c,p)
__device__ float g_st1[BATCH * CH];
__device__ float g_st2[BATCH * CMID];
__device__ float g_d1 [BATCH * CMID];
__device__ float g_d2 [BATCH * CH];

struct ResArr { int r[16]; };

// ---------------------------------------------------------------------------
// f32x2 packed-math helpers (Blackwell packed FP32 pipe)
// ---------------------------------------------------------------------------
__device__ __forceinline__ void ffma2(u64& acc, u64 a, u64 b) {
    asm("fma.rn.f32x2 %0, %1, %2, %0;" : "+l"(acc) : "l"(a), "l"(b));
}
__device__ __forceinline__ u64 pack2(float x) {
    u64 r;
    asm("mov.b64 %0, {%1, %1};" : "=l"(r) : "r"(__float_as_uint(x)));
    return r;
}
__device__ __forceinline__ void unpack2(u64 v, float& lo, float& hi) {
    unsigned a, b;
    asm("mov.b64 {%0, %1}, %2;" : "=r"(a), "=r"(b) : "l"(v));
    lo = __uint_as_float(a);
    hi = __uint_as_float(b);
}

// ---------------------------------------------------------------------------
// Styles:   st = s @ (w_aff / sqrt(512)) + b_aff
// ---------------------------------------------------------------------------
__global__ void styles_kernel(const float* __restrict__ s,
                              const float* __restrict__ w1a, const float* __restrict__ b1a,
                              const float* __restrict__ w2a, const float* __restrict__ b2a)
{
    int b = blockIdx.x;
    int t = threadIdx.x;
    float inv = 1.0f / sqrtf(512.0f);
    const float* sb = s + b * STYLE_DIM;
    if (t < CH) {
        float acc = 0.f;
        for (int k = 0; k < STYLE_DIM; ++k)
            acc += sb[k] * (w1a[k * CH + t] * inv);
        g_st1[b * CH + t] = acc + b1a[t];
    } else {
        int c = t - CH;
        float acc = 0.f;
        for (int k = 0; k < STYLE_DIM; ++k)
            acc += sb[k] * (w2a[k * CMID + c] * inv);
        g_st2[b * CMID + c] = acc + b2a[c];
    }
}

// ---------------------------------------------------------------------------
// Demodulation:  d[b,o] = rsqrt( sum_c st[b,c]^2 * sum_tap w[o,c,tap]^2 + 1e-8 )
// ---------------------------------------------------------------------------
__global__ void demod_kernel(const float* __restrict__ w1, const float* __restrict__ w2)
{
    int i = blockIdx.x * 256 + threadIdx.x;
    if (i < BATCH * CMID) {
        int b = i >> 7, o = i & 127;
        float acc = 0.f;
        for (int c = 0; c < CH; ++c) {
            float st = g_st1[b * CH + c];
            float wq = 0.f;
            const float* wp = w1 + ((size_t)o * CH + c) * 9;
            #pragma unroll
            for (int t = 0; t < 9; ++t) { float v = wp[t]; wq += v * v; }
            acc += wq * st * st;
        }
        g_d1[i] = rsqrtf(acc + 1e-8f);
    } else if (i < BATCH * CMID + BATCH * CH) {
        int j = i - BATCH * CMID;
        int b = j >> 5, o = j & 31;
        float acc = 0.f;
        for (int c = 0; c < CMID; ++c) {
            float st = g_st2[b * CMID + c];
            float wq = 0.f;
            const float* wp = w2 + ((size_t)o * CMID + c) * 9;
            #pragma unroll
            for (int t = 0; t < 9; ++t) { float v = wp[t]; wq += v * v; }
            acc += wq * st * st;
        }
        g_d2[j] = rsqrtf(acc + 1e-8f);
    }
}

// ---------------------------------------------------------------------------
// Hash retrieve: gather 4 corners per level, bilinear blend, fold in st1.
// ---------------------------------------------------------------------------
__global__ void __launch_bounds__(256) retrieve_kernel(
    const float* __restrict__ tables,   // (B, 16, T, 2)
    const float* __restrict__ coords,   // (B, P, 2)
    ResArr R)
{
    int idx = blockIdx.x * 256 + threadIdx.x;
    int b = idx >> 16;
    int p = idx & 65535;

    __shared__ float s1[CH];
    if (threadIdx.x < CH) s1[threadIdx.x] = g_st1[b * CH + threadIdx.x];
    __syncthreads();

    float cx = coords[((size_t)b * NPIX + p) * 2 + 0];
    float cy = coords[((size_t)b * NPIX + p) * 2 + 1];

    #pragma unroll
    for (int l = 0; l < 16; ++l) {
        float rf = (float)R.r[l];
        float px = cx * rf, py = cy * rf;
        float fx0 = floorf(px), fy0 = floorf(py);
        float fx = px - fx0, fy = py - fy0;
        unsigned x0 = (unsigned)fx0, y0 = (unsigned)fy0;
        unsigned hy0 = y0 * PRIME, hy1 = (y0 + 1u) * PRIME;
        unsigned h00 = (x0 ^ hy0) & 65535u;
        unsigned h10 = ((x0 + 1u) ^ hy0) & 65535u;
        unsigned h01 = (x0 ^ hy1) & 65535u;
        unsigned h11 = ((x0 + 1u) ^ hy1) & 65535u;
        const float2* tab = reinterpret_cast<const float2*>(tables) + ((size_t)(b * 16 + l) << 16);
        float2 f00 = __ldg(tab + h00);
        float2 f10 = __ldg(tab + h10);
        float2 f01 = __ldg(tab + h01);
        float2 f11 = __ldg(tab + h11);
        float w00 = (1.f - fx) * (1.f - fy), w10 = fx * (1.f - fy);
        float w01 = (1.f - fx) * fy,         w11 = fx * fy;
        float e0 = w00 * f00.x + w10 * f10.x + w01 * f01.x + w11 * f11.x;
        float e1 = w00 * f00.y + w10 * f10.y + w01 * f01.y + w11 * f11.y;
        g_x[(((size_t)b * CH + 2 * l    ) << 16) + p] = e0 * s1[2 * l];
        g_x[(((size_t)b * CH + 2 * l + 1) << 16) + p] = e1 * s1[2 * l + 1];
    }
}

// ---------------------------------------------------------------------------
// Direct 3x3 conv, SAME padding, packed f32x2 math.
// Grid: (8, 8, B * COUT/OG) — one out-channel group per block (no og loop).
// Tile: 32x32 pixels, 256 threads, 4 px/thread (along x).
// 16 out channels register-blocked as 8 packed pairs.
// x staged DUPLICATED in smem: value v stored as the 64-bit pair (v,v), so the
// FFMA2 broadcast operand is a single aligned LDS.64 (no mov.b64 packing).
// Row pitch 70 floats -> conflict-free for the 4row x 8col warp footprint.
// PASS 1: g_x(32ch) -> g_y1(128ch), epilogue: lrelu*sqrt2 * d1 * st2
// PASS 2: g_y1(128ch) -> g_tok(32ch), epilogue: linear, * d2
// ---------------------------------------------------------------------------
template<int PASS>
__global__ void __launch_bounds__(256, 2) conv3x3_kernel(
    const float* __restrict__ wgt, const float* __restrict__ bias)
{
    constexpr int CIN   = (PASS == 1) ? CH   : CMID;
    constexpr int COUT  = (PASS == 1) ? CMID : CH;
    constexpr int CHUNK = 8;
    constexpr int OG    = 16;                    // out channels per block
    constexpr int XPITCH = 70;                   // 34 duplicated pairs + pad
    constexpr int XPLANE = 34 * XPITCH;          // 2380 floats per channel

    const float* xin  = (PASS == 1) ? g_x  : g_y1;
    float*       yout = (PASS == 1) ? g_y1 : g_tok;
    const float* dsc  = (PASS == 1) ? g_d1 : g_d2;

    extern __shared__ float sm[];
    float* xs = sm;                              // [CHUNK][34][70] duplicated pairs
    float* ws = sm + CHUNK * XPLANE;             // [CHUNK][9][OG]

    int zz = blockIdx.z;
    int b  = zz / (COUT / OG);
    int og = zz - b * (COUT / OG);
    int bx = blockIdx.x * 32;
    int by = blockIdx.y * 32;
    int tid = threadIdx.x;
    int tx = (tid & 7) * 4;                      // 0..28
    int ty = tid >> 3;                           // 0..31
    const float* xb = xin + (size_t)b * CIN * NPIX;

    u64 acc[OG / 2][4];
    #pragma unroll
    for (int o = 0; o < OG / 2; ++o)
        #pragma unroll
        for (int q = 0; q < 4; ++q) acc[o][q] = 0ull;

    #pragma unroll 1
    for (int c0 = 0; c0 < CIN; c0 += CHUNK) {
        __syncthreads();
        // stage weights: ws[cc][t][o] (o-pairs contiguous for LDS.64)
        for (int i = tid; i < CHUNK * 9 * OG; i += 256) {
            int cc = i / (9 * OG);
            int r  = i - cc * (9 * OG);
            int t  = r / OG, o = r - t * OG;
            ws[i] = wgt[(((size_t)(og * OG + o) * CIN) + (c0 + cc)) * 9 + t];
        }
        // stage input tile 34x34, duplicated: (v,v) 64-bit pair per element
        for (int i = tid; i < CHUNK * 34 * 34; i += 256) {
            int cc = i / (34 * 34);
            int r = i - cc * (34 * 34);
            int rr = r / 34, col = r - rr * 34;
            int gy = by + rr - 1, gx = bx + col - 1;
            float v = 0.f;
            if ((unsigned)gy < 256u && (unsigned)gx < 256u)
                v = xb[((size_t)(c0 + cc) << 16) + gy * 256 + gx];
            *reinterpret_cast<u64*>(xs + cc * XPLANE + rr * XPITCH + 2 * col) = pack2(v);
        }
        __syncthreads();

        #pragma unroll 1
        for (int cc = 0; cc < CHUNK; ++cc) {
            const float* xr = xs + cc * XPLANE + ty * XPITCH + 2 * tx;
            const float* wb = ws + cc * (9 * OG);
            #pragma unroll
            for (int kh = 0; kh < 3; ++kh) {
                const u64* row = reinterpret_cast<const u64*>(xr + kh * XPITCH);
                u64 xv[6];
                #pragma unroll
                for (int j = 0; j < 6; ++j) xv[j] = row[j];
                #pragma unroll
                for (int kw = 0; kw < 3; ++kw) {
                    const u64* wp = reinterpret_cast<const u64*>(wb + (kh * 3 + kw) * OG);
                    #pragma unroll
                    for (int op = 0; op < OG / 2; ++op) {
                        u64 wv = wp[op];
                        ffma2(acc[op][0], wv, xv[kw + 0]);
                        ffma2(acc[op][1], wv, xv[kw + 1]);
                        ffma2(acc[op][2], wv, xv[kw + 2]);
                        ffma2(acc[op][3], wv, xv[kw + 3]);
                    }
                }
            }
        }
    }

    // epilogue
    #pragma unroll
    for (int op = 0; op < OG / 2; ++op) {
        float y0[4], y1[4];
        #pragma unroll
        for (int q = 0; q < 4; ++q) unpack2(acc[op][q], y0[q], y1[q]);
        #pragma unroll
        for (int h = 0; h < 2; ++h) {
            int oc = og * OG + 2 * op + h;
            float d  = dsc[b * COUT + oc];
            float bv = bias[oc];
            float pm = (PASS == 1) ? g_st2[b * CMID + oc] : 1.f;
            float* yp = (h == 0) ? y0 : y1;
            float r0 = yp[0] * d + bv, r1 = yp[1] * d + bv;
            float r2 = yp[2] * d + bv, r3 = yp[3] * d + bv;
            if (PASS == 1) {
                r0 = (r0 < 0.f ? 0.2f * r0 : r0) * 1.4142135623730951f * pm;
                r1 = (r1 < 0.f ? 0.2f * r1 : r1) * 1.4142135623730951f * pm;
                r2 = (r2 < 0.f ? 0.2f * r2 : r2) * 1.4142135623730951f * pm;
                r3 = (r3 < 0.f ? 0.2f * r3 : r3) * 1.4142135623730951f * pm;
            }
            float4 v; v.x = r0; v.y = r1; v.z = r2; v.w = r3;
            size_t obase = ((size_t)b * COUT + oc) * NPIX + (size_t)(by + ty) * 256 + bx + tx;
            *reinterpret_cast<float4*>(yout + obase) = v;
        }
    }
}

// ---------------------------------------------------------------------------
// Hash recon: scatter-add w * tok into output tables.
// Uses vectored no-return reductions (red.global.add.v2.f32) — 4 per level.
// ---------------------------------------------------------------------------
__device__ __forceinline__ void red2(float* p, float a, float b) {
    asm volatile("red.global.add.v2.f32 [%0], {%1, %2};"
                 :: "l"(p), "f"(a), "f"(b) : "memory");
}

__global__ void __launch_bounds__(256) recon_kernel(
    const float* __restrict__ coords, float* __restrict__ out, ResArr R)
{
    int idx = blockIdx.x * 256 + threadIdx.x;
    int b = idx >> 16;
    int p = idx & 65535;

    float cx = coords[((size_t)b * NPIX + p) * 2 + 0];
    float cy = coords[((size_t)b * NPIX + p) * 2 + 1];

    float v[CH];
    #pragma unroll
    for (int c = 0; c < CH; ++c)
        v[c] = g_tok[(((size_t)b * CH + c) << 16) + p];

    #pragma unroll
    for (int l = 0; l < 16; ++l) {
        float rf = (float)R.r[l];
        float px = cx * rf, py = cy * rf;
        float fx0 = floorf(px), fy0 = floorf(py);
        float fx = px - fx0, fy = py - fy0;
        unsigned x0 = (unsigned)fx0, y0 = (unsigned)fy0;
        unsigned hy0 = y0 * PRIME, hy1 = (y0 + 1u) * PRIME;
        unsigned h00 = (x0 ^ hy0) & 65535u;
        unsigned h10 = ((x0 + 1u) ^ hy0) & 65535u;
        unsigned h01 = (x0 ^ hy1) & 65535u;
        unsigned h11 = ((x0 + 1u) ^ hy1) & 65535u;
        float w00 = (1.f - fx) * (1.f - fy), w10 = fx * (1.f - fy);
        float w01 = (1.f - fx) * fy,         w11 = fx * fy;
        float a0 = v[2 * l], a1 = v[2 * l + 1];
        float* ob = out + ((size_t)(b * 16 + l) << 17);   // * T * 2
        red2(ob + 2 * h00, w00 * a0, w00 * a1);
        red2(ob + 2 * h10, w10 * a0, w10 * a1);
        red2(ob + 2 * h01, w01 * a0, w01 * a1);
        red2(ob + 2 * h11, w11 * a0, w11 * a1);
    }
}

// ---------------------------------------------------------------------------
// Launcher
// ---------------------------------------------------------------------------
extern "C" void kernel_launch(void* const* d_in, const int* in_sizes, int n_in,
                              void* d_out, int out_size)
{
    const float* inputs = (const float*)d_in[0];
    const float* s      = (const float*)d_in[1];
    const float* coords = (const float*)d_in[2];
    const float* w1_aff = (const float*)d_in[3];
    const float* b1_aff = (const float*)d_in[4];
    const float* w1     = (const float*)d_in[5];
    const float* b1     = (const float*)d_in[6];
    const float* w2_aff = (const float*)d_in[7];
    const float* b2_aff = (const float*)d_in[8];
    const float* w2     = (const float*)d_in[9];
    const float* b2     = (const float*)d_in[10];
    float* out = (float*)d_out;

    // Level resolutions: same double-precision libm sequence as the reference.
    ResArr R;
    double bb = exp((log(256.0) - log(16.0)) / 15.0);
    for (int l = 0; l < 16; ++l)
        R.r[l] = (int)floor(16.0 * pow(bb, (double)l));

    const int SMEM_BYTES = (8 * 34 * 70 + 8 * 9 * 16) * (int)sizeof(float); // 80768 B
    cudaFuncSetAttribute(conv3x3_kernel<1>, cudaFuncAttributeMaxDynamicSharedMemorySize, SMEM_BYTES);
    cudaFuncSetAttribute(conv3x3_kernel<2>, cudaFuncAttributeMaxDynamicSharedMemorySize, SMEM_BYTES);

    cudaMemsetAsync(d_out, 0, (size_t)out_size * sizeof(float));

    styles_kernel<<<BATCH, CH + CMID>>>(s, w1_aff, b1_aff, w2_aff, b2_aff);
    demod_kernel<<<5, 256>>>(w1, w2);

    retrieve_kernel<<<(BATCH * NPIX) / 256, 256>>>(inputs, coords, R);

    dim3 cgrid1(8, 8, BATCH * (CMID / 16));
    conv3x3_kernel<1><<<cgrid1, 256, SMEM_BYTES>>>(w1, b1);
    dim3 cgrid2(8, 8, BATCH * (CH / 16));
    conv3x3_kernel<2><<<cgrid2, 256, SMEM_BYTES>>>(w2, b2);

    recon_kernel<<<(BATCH * NPIX) / 256, 256>>>(coords, out, R);
}

// round 6
// speedup vs baseline: 2.2839x; 1.7085x over previous
#include <cuda_runtime.h>
#include <cuda_bf16.h>
#include <math.h>

#define TABLE_NUM 16
#define STYLE_DIM 512
#define CH 32
#define CMID 128
#define BATCH 8
#define NPIX 65536
#define PRIME 2654435761u
#define PDIM 258
#define PPIX (PDIM*PDIM)

typedef unsigned long long u64;
typedef unsigned int u32;

struct ResArr { int r[16]; };

__device__ float g_x  [(size_t)BATCH * CH * NPIX];
__device__ float g_tok[(size_t)BATCH * CH * NPIX];
__device__ u32 g_xa1[(size_t)BATCH * PPIX * 32];    // padded [xh16|xl16] u32/px
__device__ u32 g_xa2[(size_t)BATCH * PPIX * 128];   // padded [xh64|xl64] u32/px
__device__ u32 g_w1e[3 * 9 * 128 * 16];             // seg0,1=wh seg2=wl
__device__ u32 g_w2e[3 * 9 * 32 * 64];
__device__ float g_st1[BATCH * CH];
__device__ float g_st2[BATCH * CMID];
__device__ float g_d1 [BATCH * CMID];
__device__ float g_d2 [BATCH * CH];

__device__ __forceinline__ float bfround(float v) {
    return __bfloat162float(__float2bfloat16_rn(v));
}
__device__ __forceinline__ u32 packbf(float lo, float hi) {
    u32 l = (u32)__bfloat16_as_ushort(__float2bfloat16_rn(lo));
    u32 h = (u32)__bfloat16_as_ushort(__float2bfloat16_rn(hi));
    return l | (h << 16);
}
__device__ __forceinline__ void mma16816(float* c, u32 a0, u32 a1, u32 a2, u32 a3,
                                         u32 b0, u32 b1) {
    asm volatile(
        "mma.sync.aligned.m16n8k16.row.col.f32.bf16.bf16.f32 "
        "{%0,%1,%2,%3}, {%4,%5,%6,%7}, {%8,%9}, {%0,%1,%2,%3};"
        : "+f"(c[0]), "+f"(c[1]), "+f"(c[2]), "+f"(c[3])
        : "r"(a0), "r"(a1), "r"(a2), "r"(a3), "r"(b0), "r"(b1));
}

__global__ void styles_kernel(const float* __restrict__ s,
                              const float* __restrict__ w1a, const float* __restrict__ b1a,
                              const float* __restrict__ w2a, const float* __restrict__ b2a)
{
    int b = blockIdx.x, t = threadIdx.x;
    float inv = 1.0f / sqrtf(512.0f);
    const float* sb = s + b * STYLE_DIM;
    if (t < CH) {
        float acc = 0.f;
        for (int k = 0; k < STYLE_DIM; ++k) acc += sb[k] * (w1a[k * CH + t] * inv);
        g_st1[b * CH + t] = acc + b1a[t];
    } else {
        int c = t - CH;
        float acc = 0.f;
        for (int k = 0; k < STYLE_DIM; ++k) acc += sb[k] * (w2a[k * CMID + c] * inv);
        g_st2[b * CMID + c] = acc + b2a[c];
    }
}

__global__ void demod_kernel(const float* __restrict__ w1, const float* __restrict__ w2)
{
    int i = blockIdx.x * 256 + threadIdx.x;
    if (i < BATCH * CMID) {
        int b = i >> 7, o = i & 127;
        float acc = 0.f;
        for (int c = 0; c < CH; ++c) {
            float st = g_st1[b * CH + c], wq = 0.f;
            const float* wp = w1 + ((size_t)o * CH + c) * 9;
            #pragma unroll
            for (int t = 0; t < 9; ++t) { float v = wp[t]; wq += v * v; }
            acc += wq * st * st;
        }
        g_d1[i] = rsqrtf(acc + 1e-8f);
    } else if (i < BATCH * CMID + BATCH * CH) {
        int j = i - BATCH * CMID;
        int b = j >> 5, o = j & 31;
        float acc = 0.f;
        for (int c = 0; c < CMID; ++c) {
            float st = g_st2[b * CMID + c], wq = 0.f;
            const float* wp = w2 + ((size_t)o * CMID + c) * 9;
            #pragma unroll
            for (int t = 0; t < 9; ++t) { float v = wp[t]; wq += v * v; }
            acc += wq * st * st;
        }
        g_d2[j] = rsqrtf(acc + 1e-8f);
    }
}

__global__ void __launch_bounds__(256) retrieve_kernel(
    const float* __restrict__ tables, const float* __restrict__ coords, ResArr R)
{
    int idx = blockIdx.x * 256 + threadIdx.x;
    int b = idx >> 16, p = idx & 65535;
    __shared__ float s1[CH];
    if (threadIdx.x < CH) s1[threadIdx.x] = g_st1[b * CH + threadIdx.x];
    __syncthreads();
    float cx = coords[((size_t)b * NPIX + p) * 2 + 0];
    float cy = coords[((size_t)b * NPIX + p) * 2 + 1];
    #pragma unroll
    for (int l = 0; l < 16; ++l) {
        float rf = (float)R.r[l];
        float px = cx * rf, py = cy * rf;
        float fx0 = floorf(px), fy0 = floorf(py);
        float fx = px - fx0, fy = py - fy0;
        unsigned x0 = (unsigned)fx0, y0 = (unsigned)fy0;
        unsigned hy0 = y0 * PRIME, hy1 = (y0 + 1u) * PRIME;
        unsigned h00 = (x0 ^ hy0) & 65535u, h10 = ((x0 + 1u) ^ hy0) & 65535u;
        unsigned h01 = (x0 ^ hy1) & 65535u, h11 = ((x0 + 1u) ^ hy1) & 65535u;
        const float2* tab = reinterpret_cast<const float2*>(tables) + ((size_t)(b * 16 + l) << 16);
        float2 f00 = __ldg(tab + h00), f10 = __ldg(tab + h10);
        float2 f01 = __ldg(tab + h01), f11 = __ldg(tab + h11);
        float w00 = (1.f - fx) * (1.f - fy), w10 = fx * (1.f - fy);
        float w01 = (1.f - fx) * fy,         w11 = fx * fy;
        float e0 = w00 * f00.x + w10 * f10.x + w01 * f01.x + w11 * f11.x;
        float e1 = w00 * f00.y + w10 * f10.y + w01 * f01.y + w11 * f11.y;
        g_x[(((size_t)b * CH + 2 * l    ) << 16) + p] = e0 * s1[2 * l];
        g_x[(((size_t)b * CH + 2 * l + 1) << 16) + p] = e1 * s1[2 * l + 1];
    }
}

// planar g_x -> padded split rows g_xa1
__global__ void __launch_bounds__(256) split1_kernel()
{
    __shared__ u32 sm[256 * 33];
    int blk = blockIdx.x;
    int b = blk >> 8, gy = blk & 255;
    int gx = threadIdx.x;
    const float* xb = g_x + (size_t)b * CH * NPIX + gy * 256 + gx;
    #pragma unroll
    for (int j = 0; j < 16; ++j) {
        float v0 = xb[((size_t)(2 * j)) << 16];
        float v1 = xb[((size_t)(2 * j + 1)) << 16];
        sm[gx * 33 + j]      = packbf(v0, v1);
        sm[gx * 33 + 16 + j] = packbf(v0 - bfround(v0), v1 - bfround(v1));
    }
    __syncthreads();
    size_t rowbase = ((size_t)b * PPIX + (size_t)(gy + 1) * PDIM + 1) * 32;
    for (int i = threadIdx.x; i < 256 * 32; i += 256) {
        int r = i >> 5, j = i & 31;
        g_xa1[rowbase + (size_t)r * 32 + j] = sm[r * 33 + j];
    }
}

__global__ void wsplit_kernel(const float* __restrict__ w1, const float* __restrict__ w2)
{
    int i = blockIdx.x * 256 + threadIdx.x;
    if (i < 3 * 9 * 128 * 16) {
        int j = i & 15, rest = i >> 4;
        int o = rest & 127; rest >>= 7;
        int t = rest % 9, s = rest / 9;
        float va = w1[((size_t)o * 32 + 2 * j) * 9 + t];
        float vb = w1[((size_t)o * 32 + 2 * j + 1) * 9 + t];
        if (s == 2) { va -= bfround(va); vb -= bfround(vb); }
        g_w1e[i] = packbf(va, vb);
    } else {
        int i2 = i - 3 * 9 * 128 * 16;
        if (i2 < 3 * 9 * 32 * 64) {
            int j = i2 & 63, rest = i2 >> 6;
            int o = rest & 31; rest >>= 5;
            int t = rest % 9, s = rest / 9;
            float va = w2[((size_t)o * 128 + 2 * j) * 9 + t];
            float vb = w2[((size_t)o * 128 + 2 * j + 1) * 9 + t];
            if (s == 2) { va -= bfround(va); vb -= bfround(vb); }
            g_w2e[i2] = packbf(va, vb);
        }
    }
}

__global__ void border_kernel()
{
    int cell = blockIdx.x;
    int b = cell / 1032, e = cell % 1032;
    int gy, gx;
    if      (e < 258) { gy = 0;       gx = e; }
    else if (e < 516) { gy = 257;     gx = e - 258; }
    else if (e < 774) { gy = e - 516; gx = 0; }
    else              { gy = e - 774; gx = 257; }
    size_t p = (size_t)b * PPIX + (size_t)gy * PDIM + gx;
    int t = threadIdx.x;
    if (t < 32) g_xa1[p * 32 + t] = 0u;
    else        g_xa2[p * 128 + (t - 32)] = 0u;
}

// implicit-GEMM 3x3 conv on mma.sync, 3-term bf16 split.
// tile 256 px (8gy x 32gx), 8 warps x 2 M-frags; PASS1 per-block cout half.
template<int PASS>
__global__ void __launch_bounds__(256, 2) convmma_kernel(const float* __restrict__ bias)
{
    constexpr int COUT  = (PASS == 1) ? 128 : 32;
    constexpr int COUTB = (PASS == 1) ? 64  : 32;
    constexpr int KSEG  = (PASS == 1) ? 16  : 64;   // u32 per half-row
    constexpr int KROW  = (PASS == 1) ? 32  : 128;
    constexpr int AP    = (PASS == 1) ? 20  : 68;   // ≡4·odd mod 32
    constexpr int BP    = AP;
    constexpr int KC    = KSEG / 8;
    constexpr int NF    = COUTB / 8;
    constexpr int DP    = (PASS == 1) ? 68 : 36;
    constexpr int ASZ   = 340 * AP;

    extern __shared__ float smf[];
    u32* sA = reinterpret_cast<u32*>(smf);
    u32* sB = sA + ASZ;
    float* sD = smf;
    __shared__ float s_d[COUTB], s_b[COUTB], s_m[COUTB];

    const u32* gin = (PASS == 1) ? g_xa1 : g_xa2;
    const u32* we  = (PASS == 1) ? g_w1e : g_w2e;
    const float* dsc = (PASS == 1) ? g_d1 : g_d2;

    int zz = blockIdx.z;
    int bb = (PASS == 1) ? (zz >> 1) : zz;
    int og = (PASS == 1) ? (zz & 1)  : 0;
    int gy0 = blockIdx.y * 8, gx0 = blockIdx.x * 32;
    int tid = threadIdx.x;
    int w = tid >> 5, lane = tid & 31, g = lane >> 2, tig = lane & 3;
    int qrow = w >> 1, qcol = (w & 1) * 16 + g;

    if (tid < COUTB) {
        s_d[tid] = dsc[bb * COUT + og * COUTB + tid];
        s_b[tid] = bias[og * COUTB + tid];
        s_m[tid] = (PASS == 1) ? g_st2[bb * CMID + og * COUTB + tid] * 1.4142135623730951f : 0.f;
    }

    size_t abase = (size_t)bb * PPIX;
    float acc[2][NF][4];
    #pragma unroll
    for (int rb = 0; rb < 2; ++rb)
        #pragma unroll
        for (int n = 0; n < NF; ++n)
            #pragma unroll
            for (int q = 0; q < 4; ++q) acc[rb][n][q] = 0.f;

    #pragma unroll 1
    for (int si = 0; si < 3; ++si) {
        const int s = (si == 0) ? 0 : (si == 1) ? 2 : 1;   // xh*wh, xh*wl, xl*wh
        if (si != 1) {
            int segoff = (si == 2) ? KSEG : 0;
            __syncthreads();
            for (int i = tid; i < 340 * (KSEG / 4); i += 256) {
                int r = i / (KSEG / 4), w4 = i - r * (KSEG / 4);
                int sy = r / 34, sx = r - sy * 34;
                size_t p = abase + (size_t)(gy0 + sy) * PDIM + gx0 + sx;
                uint4 v = *reinterpret_cast<const uint4*>(gin + p * KROW + segoff + w4 * 4);
                *reinterpret_cast<uint4*>(sA + r * AP + w4 * 4) = v;
            }
        }
        #pragma unroll 1
        for (int tap = 0; tap < 9; ++tap) {
            __syncthreads();
            for (int i = tid; i < COUTB * (KSEG / 4); i += 256) {
                int o = i / (KSEG / 4), w4 = i - o * (KSEG / 4);
                uint4 v = *reinterpret_cast<const uint4*>(
                    we + ((size_t)((s * 9 + tap) * COUT + og * COUTB + o)) * KSEG + w4 * 4);
                *reinterpret_cast<uint4*>(sB + o * BP + w4 * 4) = v;
            }
            __syncthreads();
            int ty = tap / 3, tx = tap - 3 * (tap / 3);
            int rbase = (qrow + ty) * 34 + qcol + tx;
            #pragma unroll
            for (int kc = 0; kc < KC; ++kc) {
                u32 a[2][4];
                #pragma unroll
                for (int rb = 0; rb < 2; ++rb) {
                    const u32* p0 = sA + (rbase + rb * 136) * AP + kc * 8;
                    const u32* p1 = p0 + 8 * AP;
                    a[rb][0] = p0[tig]; a[rb][2] = p0[tig + 4];
                    a[rb][1] = p1[tig]; a[rb][3] = p1[tig + 4];
                }
                #pragma unroll
                for (int nf = 0; nf < NF; ++nf) {
                    const u32* pb = sB + (nf * 8 + g) * BP + kc * 8 + tig;
                    u32 b0 = pb[0], b1 = pb[4];
                    mma16816(acc[0][nf], a[0][0], a[0][1], a[0][2], a[0][3], b0, b1);
                    mma16816(acc[1][nf], a[1][0], a[1][1], a[1][2], a[1][3], b0, b1);
                }
            }
        }
    }

    // epilogue in two 128-px chunks (chunk == M rowblock)
    #pragma unroll 1
    for (int rb = 0; rb < 2; ++rb) {
        __syncthreads();
        int q0 = w * 16 + g;
        #pragma unroll
        for (int nf = 0; nf < NF; ++nf) {
            int cb = nf * 8 + 2 * tig;
            float d0 = s_d[cb], d1 = s_d[cb + 1];
            float b0 = s_b[cb], b1 = s_b[cb + 1];
            float y00 = acc[rb][nf][0] * d0 + b0, y01 = acc[rb][nf][1] * d1 + b1;
            float y10 = acc[rb][nf][2] * d0 + b0, y11 = acc[rb][nf][3] * d1 + b1;
            if (PASS == 1) {
                float m0 = s_m[cb], m1 = s_m[cb + 1];
                y00 = (y00 < 0.f ? 0.2f * y00 : y00) * m0;
                y01 = (y01 < 0.f ? 0.2f * y01 : y01) * m1;
                y10 = (y10 < 0.f ? 0.2f * y10 : y10) * m0;
                y11 = (y11 < 0.f ? 0.2f * y11 : y11) * m1;
            }
            sD[q0 * DP + cb] = y00; sD[q0 * DP + cb + 1] = y01;
            sD[(q0 + 8) * DP + cb] = y10; sD[(q0 + 8) * DP + cb + 1] = y11;
        }
        __syncthreads();
        if (PASS == 1) {
            for (int i = tid; i < 128 * 16; i += 256) {
                int q = i >> 4, t = i & 15;
                float4 y = *reinterpret_cast<const float4*>(sD + q * DP + 4 * t);
                u32 xh0 = packbf(y.x, y.y), xh1 = packbf(y.z, y.w);
                u32 xl0 = packbf(y.x - bfround(y.x), y.y - bfround(y.y));
                u32 xl1 = packbf(y.z - bfround(y.z), y.w - bfround(y.w));
                int gy = gy0 + rb * 4 + (q >> 5), gx = gx0 + (q & 31);
                u32* row = g_xa2 + (abase + (size_t)(gy + 1) * PDIM + gx + 1) * 128;
                int wj = og * 32 + 2 * t;
                *reinterpret_cast<u64*>(row + wj)      = (u64)xh0 | ((u64)xh1 << 32);
                *reinterpret_cast<u64*>(row + 64 + wj) = (u64)xl0 | ((u64)xl1 << 32);
            }
        } else {
            for (int i = tid; i < 32 * 128; i += 256) {
                int c = i >> 7, q = i & 127;
                float v = sD[q * DP + c];
                int gy = gy0 + rb * 4 + (q >> 5), gx = gx0 + (q & 31);
                g_tok[((size_t)bb * CH + c) * NPIX + gy * 256 + gx] = v;
            }
        }
    }
}

__device__ __forceinline__ void red2(float* p, float a, float b) {
    asm volatile("red.global.add.v2.f32 [%0], {%1, %2};"
                 :: "l"(p), "f"(a), "f"(b) : "memory");
}

__global__ void __launch_bounds__(256) recon_kernel(
    const float* __restrict__ coords, float* __restrict__ out, ResArr R)
{
    int idx = blockIdx.x * 256 + threadIdx.x;
    int b = idx >> 16, p = idx & 65535;
    float cx = coords[((size_t)b * NPIX + p) * 2 + 0];
    float cy = coords[((size_t)b * NPIX + p) * 2 + 1];
    float v[CH];
    #pragma unroll
    for (int c = 0; c < CH; ++c)
        v[c] = g_tok[(((size_t)b * CH + c) << 16) + p];
    #pragma unroll
    for (int l = 0; l < 16; ++l) {
        float rf = (float)R.r[l];
        float px = cx * rf, py = cy * rf;
        float fx0 = floorf(px), fy0 = floorf(py);
        float fx = px - fx0, fy = py - fy0;
        unsigned x0 = (unsigned)fx0, y0 = (unsigned)fy0;
        unsigned hy0 = y0 * PRIME, hy1 = (y0 + 1u) * PRIME;
        unsigned h00 = (x0 ^ hy0) & 65535u, h10 = ((x0 + 1u) ^ hy0) & 65535u;
        unsigned h01 = (x0 ^ hy1) & 65535u, h11 = ((x0 + 1u) ^ hy1) & 65535u;
        float w00 = (1.f - fx) * (1.f - fy), w10 = fx * (1.f - fy);
        float w01 = (1.f - fx) * fy,         w11 = fx * fy;
        float a0 = v[2 * l], a1 = v[2 * l + 1];
        float* ob = out + ((size_t)(b * 16 + l) << 17);
        red2(ob + 2 * h00, w00 * a0, w00 * a1);
        red2(ob + 2 * h10, w10 * a0, w10 * a1);
        red2(ob + 2 * h01, w01 * a0, w01 * a1);
        red2(ob + 2 * h11, w11 * a0, w11 * a1);
    }
}

extern "C" void kernel_launch(void* const* d_in, const int* in_sizes, int n_in,
                              void* d_out, int out_size)
{
    const float* inputs = (const float*)d_in[0];
    const float* s      = (const float*)d_in[1];
    const float* coords = (const float*)d_in[2];
    const float* w1_aff = (const float*)d_in[3];
    const float* b1_aff = (const float*)d_in[4];
    const float* w1     = (const float*)d_in[5];
    const float* b1     = (const float*)d_in[6];
    const float* w2_aff = (const float*)d_in[7];
    const float* b2_aff = (const float*)d_in[8];
    const float* w2     = (const float*)d_in[9];
    const float* b2     = (const float*)d_in[10];
    float* out = (float*)d_out;

    ResArr R;
    double bb = exp((log(256.0) - log(16.0)) / 15.0);
    for (int l = 0; l < 16; ++l)
        R.r[l] = (int)floor(16.0 * pow(bb, (double)l));

    const int SM1 = 128 * 68 * 4;                       // 34816
    const int SM2 = (340 * 68 + 32 * 68) * 4;           // 101184
    cudaFuncSetAttribute(convmma_kernel<1>, cudaFuncAttributeMaxDynamicSharedMemorySize, SM1);
    cudaFuncSetAttribute(convmma_kernel<2>, cudaFuncAttributeMaxDynamicSharedMemorySize, SM2);

    cudaMemsetAsync(d_out, 0, (size_t)out_size * sizeof(float));

    styles_kernel<<<BATCH, CH + CMID>>>(s, w1_aff, b1_aff, w2_aff, b2_aff);
    demod_kernel<<<5, 256>>>(w1, w2);
    wsplit_kernel<<<432, 256>>>(w1, w2);
    retrieve_kernel<<<(BATCH * NPIX) / 256, 256>>>(inputs, coords, R);
    split1_kernel<<<BATCH * 256, 256>>>();
    border_kernel<<<BATCH * 1032, 160>>>();

    dim3 cg1(8, 32, BATCH * 2);
    convmma_kernel<1><<<cg1, 256, SM1>>>(b1);
    dim3 cg2(8, 32, BATCH);
    convmma_kernel<2><<<cg2, 256, SM2>>>(b2);

    recon_kernel<<<(BATCH * NPIX) / 256, 256>>>(coords, out, R);
}

// round 7
// speedup vs baseline: 2.3038x; 1.0087x over previous
#include <cuda_runtime.h>
#include <cuda_bf16.h>
#include <math.h>

#define TABLE_NUM 16
#define STYLE_DIM 512
#define CH 32
#define CMID 128
#define BATCH 8
#define NPIX 65536
#define PRIME 2654435761u
#define PDIM 258
#define PPIX (PDIM*PDIM)

typedef unsigned long long u64;
typedef unsigned int u32;

struct ResArr { int r[16]; };

__device__ float g_tok[(size_t)BATCH * CH * NPIX];
__device__ u32 g_xa1[(size_t)BATCH * PPIX * 32];    // padded [xh16|xl16] u32/px
__device__ u32 g_xa2[(size_t)BATCH * PPIX * 128];   // padded [xh64|xl64] u32/px
__device__ u32 g_w1e[3 * 9 * 128 * 16];             // seg0,1=wh seg2=wl
__device__ u32 g_w2e[3 * 9 * 32 * 64];
__device__ float g_st1[BATCH * CH];
__device__ float g_st2[BATCH * CMID];
__device__ float g_d1 [BATCH * CMID];
__device__ float g_d2 [BATCH * CH];

__device__ __forceinline__ float bfround(float v) {
    return __bfloat162float(__float2bfloat16_rn(v));
}
__device__ __forceinline__ u32 packbf(float lo, float hi) {
    u32 l = (u32)__bfloat16_as_ushort(__float2bfloat16_rn(lo));
    u32 h = (u32)__bfloat16_as_ushort(__float2bfloat16_rn(hi));
    return l | (h << 16);
}
__device__ __forceinline__ void mma16816(float* c, u32 a0, u32 a1, u32 a2, u32 a3,
                                         u32 b0, u32 b1) {
    asm volatile(
        "mma.sync.aligned.m16n8k16.row.col.f32.bf16.bf16.f32 "
        "{%0,%1,%2,%3}, {%4,%5,%6,%7}, {%8,%9}, {%0,%1,%2,%3};"
        : "+f"(c[0]), "+f"(c[1]), "+f"(c[2]), "+f"(c[3])
        : "r"(a0), "r"(a1), "r"(a2), "r"(a3), "r"(b0), "r"(b1));
}
__device__ __forceinline__ void ldsm4(u32& r0, u32& r1, u32& r2, u32& r3, u32 addr) {
    asm volatile("ldmatrix.sync.aligned.m8n8.x4.shared.b16 {%0,%1,%2,%3}, [%4];"
                 : "=r"(r0), "=r"(r1), "=r"(r2), "=r"(r3) : "r"(addr));
}
__device__ __forceinline__ u32 smem_u32(const void* p) {
    return (u32)__cvta_generic_to_shared(p);
}

__global__ void styles_kernel(const float* __restrict__ s,
                              const float* __restrict__ w1a, const float* __restrict__ b1a,
                              const float* __restrict__ w2a, const float* __restrict__ b2a)
{
    int b = blockIdx.x, t = threadIdx.x;
    float inv = 1.0f / sqrtf(512.0f);
    const float* sb = s + b * STYLE_DIM;
    if (t < CH) {
        float acc = 0.f;
        for (int k = 0; k < STYLE_DIM; ++k) acc += sb[k] * (w1a[k * CH + t] * inv);
        g_st1[b * CH + t] = acc + b1a[t];
    } else {
        int c = t - CH;
        float acc = 0.f;
        for (int k = 0; k < STYLE_DIM; ++k) acc += sb[k] * (w2a[k * CMID + c] * inv);
        g_st2[b * CMID + c] = acc + b2a[c];
    }
}

__global__ void demod_kernel(const float* __restrict__ w1, const float* __restrict__ w2)
{
    int i = blockIdx.x * 256 + threadIdx.x;
    if (i < BATCH * CMID) {
        int b = i >> 7, o = i & 127;
        float acc = 0.f;
        for (int c = 0; c < CH; ++c) {
            float st = g_st1[b * CH + c], wq = 0.f;
            const float* wp = w1 + ((size_t)o * CH + c) * 9;
            #pragma unroll
            for (int t = 0; t < 9; ++t) { float v = wp[t]; wq += v * v; }
            acc += wq * st * st;
        }
        g_d1[i] = rsqrtf(acc + 1e-8f);
    } else if (i < BATCH * CMID + BATCH * CH) {
        int j = i - BATCH * CMID;
        int b = j >> 5, o = j & 31;
        float acc = 0.f;
        for (int c = 0; c < CMID; ++c) {
            float st = g_st2[b * CMID + c], wq = 0.f;
            const float* wp = w2 + ((size_t)o * CMID + c) * 9;
            #pragma unroll
            for (int t = 0; t < 9; ++t) { float v = wp[t]; wq += v * v; }
            acc += wq * st * st;
        }
        g_d2[j] = rsqrtf(acc + 1e-8f);
    }
}

// retrieve fused with split: writes padded split-bf16 rows of g_xa1 directly
__global__ void __launch_bounds__(256) retrieve_kernel(
    const float* __restrict__ tables, const float* __restrict__ coords, ResArr R)
{
    int idx = blockIdx.x * 256 + threadIdx.x;
    int b = idx >> 16, p = idx & 65535;
    __shared__ float s1[CH];
    if (threadIdx.x < CH) s1[threadIdx.x] = g_st1[b * CH + threadIdx.x];
    __syncthreads();
    float cx = coords[((size_t)b * NPIX + p) * 2 + 0];
    float cy = coords[((size_t)b * NPIX + p) * 2 + 1];
    u32 ov[32];
    #pragma unroll
    for (int l = 0; l < 16; ++l) {
        float rf = (float)R.r[l];
        float px = cx * rf, py = cy * rf;
        float fx0 = floorf(px), fy0 = floorf(py);
        float fx = px - fx0, fy = py - fy0;
        unsigned x0 = (unsigned)fx0, y0 = (unsigned)fy0;
        unsigned hy0 = y0 * PRIME, hy1 = (y0 + 1u) * PRIME;
        unsigned h00 = (x0 ^ hy0) & 65535u, h10 = ((x0 + 1u) ^ hy0) & 65535u;
        unsigned h01 = (x0 ^ hy1) & 65535u, h11 = ((x0 + 1u) ^ hy1) & 65535u;
        const float2* tab = reinterpret_cast<const float2*>(tables) + ((size_t)(b * 16 + l) << 16);
        float2 f00 = __ldg(tab + h00), f10 = __ldg(tab + h10);
        float2 f01 = __ldg(tab + h01), f11 = __ldg(tab + h11);
        float w00 = (1.f - fx) * (1.f - fy), w10 = fx * (1.f - fy);
        float w01 = (1.f - fx) * fy,         w11 = fx * fy;
        float e0 = (w00 * f00.x + w10 * f10.x + w01 * f01.x + w11 * f11.x) * s1[2 * l];
        float e1 = (w00 * f00.y + w10 * f10.y + w01 * f01.y + w11 * f11.y) * s1[2 * l + 1];
        ov[l]      = packbf(e0, e1);
        ov[16 + l] = packbf(e0 - bfround(e0), e1 - bfround(e1));
    }
    int gy = p >> 8, gx = p & 255;
    u32* row = g_xa1 + ((size_t)b * PPIX + (size_t)(gy + 1) * PDIM + gx + 1) * 32;
    #pragma unroll
    for (int j = 0; j < 8; ++j)
        *reinterpret_cast<uint4*>(row + 4 * j) =
            make_uint4(ov[4 * j], ov[4 * j + 1], ov[4 * j + 2], ov[4 * j + 3]);
}

__global__ void wsplit_kernel(const float* __restrict__ w1, const float* __restrict__ w2)
{
    int i = blockIdx.x * 256 + threadIdx.x;
    if (i < 3 * 9 * 128 * 16) {
        int j = i & 15, rest = i >> 4;
        int o = rest & 127; rest >>= 7;
        int t = rest % 9, s = rest / 9;
        float va = w1[((size_t)o * 32 + 2 * j) * 9 + t];
        float vb = w1[((size_t)o * 32 + 2 * j + 1) * 9 + t];
        if (s == 2) { va -= bfround(va); vb -= bfround(vb); }
        g_w1e[i] = packbf(va, vb);
    } else {
        int i2 = i - 3 * 9 * 128 * 16;
        if (i2 < 3 * 9 * 32 * 64) {
            int j = i2 & 63, rest = i2 >> 6;
            int o = rest & 31; rest >>= 5;
            int t = rest % 9, s = rest / 9;
            float va = w2[((size_t)o * 128 + 2 * j) * 9 + t];
            float vb = w2[((size_t)o * 128 + 2 * j + 1) * 9 + t];
            if (s == 2) { va -= bfround(va); vb -= bfround(vb); }
            g_w2e[i2] = packbf(va, vb);
        }
    }
}

__global__ void border_kernel()
{
    int cell = blockIdx.x;
    int b = cell / 1032, e = cell % 1032;
    int gy, gx;
    if      (e < 258) { gy = 0;       gx = e; }
    else if (e < 516) { gy = 257;     gx = e - 258; }
    else if (e < 774) { gy = e - 516; gx = 0; }
    else              { gy = e - 774; gx = 257; }
    size_t p = (size_t)b * PPIX + (size_t)gy * PDIM + gx;
    int t = threadIdx.x;
    if (t < 32) g_xa1[p * 32 + t] = 0u;
    else        g_xa2[p * 128 + (t - 32)] = 0u;
}

// implicit-GEMM 3x3 conv on mma.sync + ldmatrix, 3-term bf16 split.
template<int PASS>
__global__ void __launch_bounds__(256, 2) convmma_kernel(const float* __restrict__ bias)
{
    constexpr int COUT  = (PASS == 1) ? 128 : 32;
    constexpr int COUTB = (PASS == 1) ? 64  : 32;
    constexpr int KSEG  = (PASS == 1) ? 16  : 64;
    constexpr int KROW  = (PASS == 1) ? 32  : 128;
    constexpr int AP    = (PASS == 1) ? 20  : 68;   // 80B / 272B pitch: LDSM-safe
    constexpr int BP    = AP;
    constexpr int KC    = KSEG / 8;
    constexpr int NF    = COUTB / 8;
    constexpr int DP    = (PASS == 1) ? 68 : 36;
    constexpr int ASZ   = 340 * AP;

    extern __shared__ float smf[];
    u32* sA = reinterpret_cast<u32*>(smf);
    u32* sB = sA + ASZ;
    float* sD = smf;
    __shared__ float s_d[COUTB], s_b[COUTB], s_m[COUTB];

    const u32* gin = (PASS == 1) ? g_xa1 : g_xa2;
    const u32* we  = (PASS == 1) ? g_w1e : g_w2e;
    const float* dsc = (PASS == 1) ? g_d1 : g_d2;

    int zz = blockIdx.z;
    int bb = (PASS == 1) ? (zz >> 1) : zz;
    int og = (PASS == 1) ? (zz & 1)  : 0;
    int gy0 = blockIdx.y * 8, gx0 = blockIdx.x * 32;
    int tid = threadIdx.x;
    int w = tid >> 5, lane = tid & 31, g = lane >> 2, tig = lane & 3;
    int qrow = w >> 1;
    int lane7 = lane & 7, l8 = (lane >> 3) & 1, l16 = (lane >> 4) & 1;

    if (tid < COUTB) {
        s_d[tid] = dsc[bb * COUT + og * COUTB + tid];
        s_b[tid] = bias[og * COUTB + tid];
        s_m[tid] = (PASS == 1) ? g_st2[bb * CMID + og * COUTB + tid] * 1.4142135623730951f : 0.f;
    }

    // ldmatrix lane address bases
    u32 saBase = smem_u32(sA), sbBase = smem_u32(sB);
    // A: lanes 0-7 m0-7 klo, 8-15 m8-15 klo, 16-23 m0-7 khi, 24-31 m8-15 khi
    int arow0 = qrow * 34 + (w & 1) * 16 + lane7 + l8 * 8;
    u32 akoff = (u32)(l16 * 16);
    // B: lanes 0-7 n0-7 klo, 8-15 n0-7 khi, 16-23 n8-15 klo, 24-31 n8-15 khi
    int brow = lane7 + l16 * 8;
    u32 bkoff = (u32)(l8 * 16);

    size_t abase = (size_t)bb * PPIX;
    float acc[2][NF][4];
    #pragma unroll
    for (int rb = 0; rb < 2; ++rb)
        #pragma unroll
        for (int n = 0; n < NF; ++n)
            #pragma unroll
            for (int q = 0; q < 4; ++q) acc[rb][n][q] = 0.f;

    #pragma unroll 1
    for (int si = 0; si < 3; ++si) {
        const int s = (si == 0) ? 0 : (si == 1) ? 2 : 1;   // xh*wh, xh*wl, xl*wh
        if (si != 1) {
            int segoff = (si == 2) ? KSEG : 0;
            __syncthreads();
            for (int i = tid; i < 340 * (KSEG / 4); i += 256) {
                int r = i / (KSEG / 4), w4 = i - r * (KSEG / 4);
                int sy = r / 34, sx = r - sy * 34;
                size_t p = abase + (size_t)(gy0 + sy) * PDIM + gx0 + sx;
                uint4 v = *reinterpret_cast<const uint4*>(gin + p * KROW + segoff + w4 * 4);
                *reinterpret_cast<uint4*>(sA + r * AP + w4 * 4) = v;
            }
        }
        #pragma unroll 1
        for (int tap = 0; tap < 9; ++tap) {
            __syncthreads();
            for (int i = tid; i < COUTB * (KSEG / 4); i += 256) {
                int o = i / (KSEG / 4), w4 = i - o * (KSEG / 4);
                uint4 v = *reinterpret_cast<const uint4*>(
                    we + ((size_t)((s * 9 + tap) * COUT + og * COUTB + o)) * KSEG + w4 * 4);
                *reinterpret_cast<uint4*>(sB + o * BP + w4 * 4) = v;
            }
            __syncthreads();
            int ty = tap / 3, tx = tap - 3 * (tap / 3);
            int arow = arow0 + ty * 34 + tx;
            u32 aAddr = saBase + (u32)(arow * AP) * 4u + akoff;
            #pragma unroll
            for (int kc = 0; kc < KC; ++kc) {
                u32 a[2][4];
                ldsm4(a[0][0], a[0][1], a[0][2], a[0][3], aAddr + (u32)(kc * 32));
                ldsm4(a[1][0], a[1][1], a[1][2], a[1][3],
                      aAddr + (u32)(kc * 32) + (u32)(136 * AP * 4));
                #pragma unroll
                for (int j = 0; j < NF / 2; ++j) {
                    u32 b0, b1, b2, b3;
                    u32 bAddr = sbBase + (u32)(((j * 16 + brow) * BP + kc * 8) * 4) + bkoff;
                    ldsm4(b0, b1, b2, b3, bAddr);
                    mma16816(acc[0][2 * j],     a[0][0], a[0][1], a[0][2], a[0][3], b0, b1);
                    mma16816(acc[0][2 * j + 1], a[0][0], a[0][1], a[0][2], a[0][3], b2, b3);
                    mma16816(acc[1][2 * j],     a[1][0], a[1][1], a[1][2], a[1][3], b0, b1);
                    mma16816(acc[1][2 * j + 1], a[1][0], a[1][1], a[1][2], a[1][3], b2, b3);
                }
            }
        }
    }

    #pragma unroll 1
    for (int rb = 0; rb < 2; ++rb) {
        __syncthreads();
        int q0 = w * 16 + g;
        #pragma unroll
        for (int nf = 0; nf < NF; ++nf) {
            int cb = nf * 8 + 2 * tig;
            float d0 = s_d[cb], d1 = s_d[cb + 1];
            float b0 = s_b[cb], b1 = s_b[cb + 1];
            float y00 = acc[rb][nf][0] * d0 + b0, y01 = acc[rb][nf][1] * d1 + b1;
            float y10 = acc[rb][nf][2] * d0 + b0, y11 = acc[rb][nf][3] * d1 + b1;
            if (PASS == 1) {
                float m0 = s_m[cb], m1 = s_m[cb + 1];
                y00 = (y00 < 0.f ? 0.2f * y00 : y00) * m0;
                y01 = (y01 < 0.f ? 0.2f * y01 : y01) * m1;
                y10 = (y10 < 0.f ? 0.2f * y10 : y10) * m0;
                y11 = (y11 < 0.f ? 0.2f * y11 : y11) * m1;
            }
            sD[q0 * DP + cb] = y00; sD[q0 * DP + cb + 1] = y01;
            sD[(q0 + 8) * DP + cb] = y10; sD[(q0 + 8) * DP + cb + 1] = y11;
        }
        __syncthreads();
        if (PASS == 1) {
            for (int i = tid; i < 128 * 16; i += 256) {
                int q = i >> 4, t = i & 15;
                float4 y = *reinterpret_cast<const float4*>(sD + q * DP + 4 * t);
                u32 xh0 = packbf(y.x, y.y), xh1 = packbf(y.z, y.w);
                u32 xl0 = packbf(y.x - bfround(y.x), y.y - bfround(y.y));
                u32 xl1 = packbf(y.z - bfround(y.z), y.w - bfround(y.w));
                int gy = gy0 + rb * 4 + (q >> 5), gx = gx0 + (q & 31);
                u32* row = g_xa2 + (abase + (size_t)(gy + 1) * PDIM + gx + 1) * 128;
                int wj = og * 32 + 2 * t;
                *reinterpret_cast<u64*>(row + wj)      = (u64)xh0 | ((u64)xh1 << 32);
                *reinterpret_cast<u64*>(row + 64 + wj) = (u64)xl0 | ((u64)xl1 << 32);
            }
        } else {
            for (int i = tid; i < 32 * 128; i += 256) {
                int c = i >> 7, q = i & 127;
                float v = sD[q * DP + c];
                int gy = gy0 + rb * 4 + (q >> 5), gx = gx0 + (q & 31);
                g_tok[((size_t)bb * CH + c) * NPIX + gy * 256 + gx] = v;
            }
        }
    }
}

__device__ __forceinline__ void red2(float* p, float a, float b) {
    asm volatile("red.global.add.v2.f32 [%0], {%1, %2};"
                 :: "l"(p), "f"(a), "f"(b) : "memory");
}

__global__ void __launch_bounds__(256) recon_kernel(
    const float* __restrict__ coords, float* __restrict__ out, ResArr R)
{
    int idx = blockIdx.x * 256 + threadIdx.x;
    int b = idx >> 16, p = idx & 65535;
    float cx = coords[((size_t)b * NPIX + p) * 2 + 0];
    float cy = coords[((size_t)b * NPIX + p) * 2 + 1];
    float v[CH];
    #pragma unroll
    for (int c = 0; c < CH; ++c)
        v[c] = g_tok[(((size_t)b * CH + c) << 16) + p];
    #pragma unroll
    for (int l = 0; l < 16; ++l) {
        float rf = (float)R.r[l];
        float px = cx * rf, py = cy * rf;
        float fx0 = floorf(px), fy0 = floorf(py);
        float fx = px - fx0, fy = py - fy0;
        unsigned x0 = (unsigned)fx0, y0 = (unsigned)fy0;
        unsigned hy0 = y0 * PRIME, hy1 = (y0 + 1u) * PRIME;
        unsigned h00 = (x0 ^ hy0) & 65535u, h10 = ((x0 + 1u) ^ hy0) & 65535u;
        unsigned h01 = (x0 ^ hy1) & 65535u, h11 = ((x0 + 1u) ^ hy1) & 65535u;
        float w00 = (1.f - fx) * (1.f - fy), w10 = fx * (1.f - fy);
        float w01 = (1.f - fx) * fy,         w11 = fx * fy;
        float a0 = v[2 * l], a1 = v[2 * l + 1];
        float* ob = out + ((size_t)(b * 16 + l) << 17);
        red2(ob + 2 * h00, w00 * a0, w00 * a1);
        red2(ob + 2 * h10, w10 * a0, w10 * a1);
        red2(ob + 2 * h01, w01 * a0, w01 * a1);
        red2(ob + 2 * h11, w11 * a0, w11 * a1);
    }
}

extern "C" void kernel_launch(void* const* d_in, const int* in_sizes, int n_in,
                              void* d_out, int out_size)
{
    const float* inputs = (const float*)d_in[0];
    const float* s      = (const float*)d_in[1];
    const float* coords = (const float*)d_in[2];
    const float* w1_aff = (const float*)d_in[3];
    const float* b1_aff = (const float*)d_in[4];
    const float* w1     = (const float*)d_in[5];
    const float* b1     = (const float*)d_in[6];
    const float* w2_aff = (const float*)d_in[7];
    const float* b2_aff = (const float*)d_in[8];
    const float* w2     = (const float*)d_in[9];
    const float* b2     = (const float*)d_in[10];
    float* out = (float*)d_out;

    ResArr R;
    double bb = exp((log(256.0) - log(16.0)) / 15.0);
    for (int l = 0; l < 16; ++l)
        R.r[l] = (int)floor(16.0 * pow(bb, (double)l));

    const int SM1 = 128 * 68 * 4;                       // 34816
    const int SM2 = (340 * 68 + 32 * 68) * 4;           // 101184
    cudaFuncSetAttribute(convmma_kernel<1>, cudaFuncAttributeMaxDynamicSharedMemorySize, SM1);
    cudaFuncSetAttribute(convmma_kernel<2>, cudaFuncAttributeMaxDynamicSharedMemorySize, SM2);

    cudaMemsetAsync(d_out, 0, (size_t)out_size * sizeof(float));

    styles_kernel<<<BATCH, CH + CMID>>>(s, w1_aff, b1_aff, w2_aff, b2_aff);
    demod_kernel<<<5, 256>>>(w1, w2);
    wsplit_kernel<<<432, 256>>>(w1, w2);
    retrieve_kernel<<<(BATCH * NPIX) / 256, 256>>>(inputs, coords, R);
    border_kernel<<<BATCH * 1032, 160>>>();

    dim3 cg1(8, 32, BATCH * 2);
    convmma_kernel<1><<<cg1, 256, SM1>>>(b1);
    dim3 cg2(8, 32, BATCH);
    convmma_kernel<2><<<cg2, 256, SM2>>>(b2);

    recon_kernel<<<(BATCH * NPIX) / 256, 256>>>(coords, out, R);
}

// round 9
// speedup vs baseline: 2.4301x; 1.0548x over previous
#include <cuda_runtime.h>
#include <cuda_bf16.h>
#include <math.h>

#define TABLE_NUM 16
#define STYLE_DIM 512
#define CH 32
#define CMID 128
#define BATCH 8
#define NPIX 65536
#define PRIME 2654435761u
#define PDIM 258
#define PPIX (PDIM*PDIM)

typedef unsigned long long u64;
typedef unsigned int u32;

struct ResArr { int r[16]; };

__device__ float g_tok[(size_t)BATCH * CH * NPIX];
__device__ u32 g_xa1[(size_t)BATCH * PPIX * 32];    // padded [xh16|xl16] u32/px
__device__ u32 g_xa2[(size_t)BATCH * PPIX * 128];   // padded [xh64|xl64] u32/px
__device__ u32 g_w1e[3 * 9 * 128 * 16];             // seg0,1=wh seg2=wl
__device__ u32 g_w2e[3 * 9 * 32 * 64];
__device__ float g_st1[BATCH * CH];
__device__ float g_st2[BATCH * CMID];
__device__ float g_d1 [BATCH * CMID];
__device__ float g_d2 [BATCH * CH];

__device__ __forceinline__ float bfround(float v) {
    return __bfloat162float(__float2bfloat16_rn(v));
}
__device__ __forceinline__ u32 packbf(float lo, float hi) {
    u32 l = (u32)__bfloat16_as_ushort(__float2bfloat16_rn(lo));
    u32 h = (u32)__bfloat16_as_ushort(__float2bfloat16_rn(hi));
    return l | (h << 16);
}
__device__ __forceinline__ void mma16816(float* c, u32 a0, u32 a1, u32 a2, u32 a3,
                                         u32 b0, u32 b1) {
    asm volatile(
        "mma.sync.aligned.m16n8k16.row.col.f32.bf16.bf16.f32 "
        "{%0,%1,%2,%3}, {%4,%5,%6,%7}, {%8,%9}, {%0,%1,%2,%3};"
        : "+f"(c[0]), "+f"(c[1]), "+f"(c[2]), "+f"(c[3])
        : "r"(a0), "r"(a1), "r"(a2), "r"(a3), "r"(b0), "r"(b1));
}
__device__ __forceinline__ void ldsm4(u32& r0, u32& r1, u32& r2, u32& r3, u32 addr) {
    asm volatile("ldmatrix.sync.aligned.m8n8.x4.shared.b16 {%0,%1,%2,%3}, [%4];"
                 : "=r"(r0), "=r"(r1), "=r"(r2), "=r"(r3) : "r"(addr));
}
__device__ __forceinline__ u32 smem_u32(const void* p) {
    return (u32)__cvta_generic_to_shared(p);
}
__device__ __forceinline__ void cpasync16(u32 dst, const void* src) {
    asm volatile("cp.async.cg.shared.global [%0], [%1], 16;" :: "r"(dst), "l"(src));
}
__device__ __forceinline__ void cp_commit() {
    asm volatile("cp.async.commit_group;" ::: "memory");
}
__device__ __forceinline__ void cp_wait0() {
    asm volatile("cp.async.wait_group 0;" ::: "memory");
}

__global__ void styles_kernel(const float* __restrict__ s,
                              const float* __restrict__ w1a, const float* __restrict__ b1a,
                              const float* __restrict__ w2a, const float* __restrict__ b2a)
{
    int b = blockIdx.x, t = threadIdx.x;
    float inv = 1.0f / sqrtf(512.0f);
    const float* sb = s + b * STYLE_DIM;
    if (t < CH) {
        float acc = 0.f;
        for (int k = 0; k < STYLE_DIM; ++k) acc += sb[k] * (w1a[k * CH + t] * inv);
        g_st1[b * CH + t] = acc + b1a[t];
    } else {
        int c = t - CH;
        float acc = 0.f;
        for (int k = 0; k < STYLE_DIM; ++k) acc += sb[k] * (w2a[k * CMID + c] * inv);
        g_st2[b * CMID + c] = acc + b2a[c];
    }
}

__global__ void demod_kernel(const float* __restrict__ w1, const float* __restrict__ w2)
{
    int i = blockIdx.x * 256 + threadIdx.x;
    if (i < BATCH * CMID) {
        int b = i >> 7, o = i & 127;
        float acc = 0.f;
        for (int c = 0; c < CH; ++c) {
            float st = g_st1[b * CH + c], wq = 0.f;
            const float* wp = w1 + ((size_t)o * CH + c) * 9;
            #pragma unroll
            for (int t = 0; t < 9; ++t) { float v = wp[t]; wq += v * v; }
            acc += wq * st * st;
        }
        g_d1[i] = rsqrtf(acc + 1e-8f);
    } else if (i < BATCH * CMID + BATCH * CH) {
        int j = i - BATCH * CMID;
        int b = j >> 5, o = j & 31;
        float acc = 0.f;
        for (int c = 0; c < CMID; ++c) {
            float st = g_st2[b * CMID + c], wq = 0.f;
            const float* wp = w2 + ((size_t)o * CMID + c) * 9;
            #pragma unroll
            for (int t = 0; t < 9; ++t) { float v = wp[t]; wq += v * v; }
            acc += wq * st * st;
        }
        g_d2[j] = rsqrtf(acc + 1e-8f);
    }
}

// retrieve fused with split: writes padded split-bf16 rows of g_xa1 directly
__global__ void __launch_bounds__(256) retrieve_kernel(
    const float* __restrict__ tables, const float* __restrict__ coords, ResArr R)
{
    int idx = blockIdx.x * 256 + threadIdx.x;
    int b = idx >> 16, p = idx & 65535;
    __shared__ float s1[CH];
    if (threadIdx.x < CH) s1[threadIdx.x] = g_st1[b * CH + threadIdx.x];
    __syncthreads();
    float cx = coords[((size_t)b * NPIX + p) * 2 + 0];
    float cy = coords[((size_t)b * NPIX + p) * 2 + 1];
    u32 ov[32];
    #pragma unroll
    for (int l = 0; l < 16; ++l) {
        float rf = (float)R.r[l];
        float px = cx * rf, py = cy * rf;
        float fx0 = floorf(px), fy0 = floorf(py);
        float fx = px - fx0, fy = py - fy0;
        unsigned x0 = (unsigned)fx0, y0 = (unsigned)fy0;
        unsigned hy0 = y0 * PRIME, hy1 = (y0 + 1u) * PRIME;
        unsigned h00 = (x0 ^ hy0) & 65535u, h10 = ((x0 + 1u) ^ hy0) & 65535u;
        unsigned h01 = (x0 ^ hy1) & 65535u, h11 = ((x0 + 1u) ^ hy1) & 65535u;
        const float2* tab = reinterpret_cast<const float2*>(tables) + ((size_t)(b * 16 + l) << 16);
        float2 f00 = __ldg(tab + h00), f10 = __ldg(tab + h10);
        float2 f01 = __ldg(tab + h01), f11 = __ldg(tab + h11);
        float w00 = (1.f - fx) * (1.f - fy), w10 = fx * (1.f - fy);
        float w01 = (1.f - fx) * fy,         w11 = fx * fy;
        float e0 = (w00 * f00.x + w10 * f10.x + w01 * f01.x + w11 * f11.x) * s1[2 * l];
        float e1 = (w00 * f00.y + w10 * f10.y + w01 * f01.y + w11 * f11.y) * s1[2 * l + 1];
        ov[l]      = packbf(e0, e1);
        ov[16 + l] = packbf(e0 - bfround(e0), e1 - bfround(e1));
    }
    int gy = p >> 8, gx = p & 255;
    u32* row = g_xa1 + ((size_t)b * PPIX + (size_t)(gy + 1) * PDIM + gx + 1) * 32;
    #pragma unroll
    for (int j = 0; j < 8; ++j)
        *reinterpret_cast<uint4*>(row + 4 * j) =
            make_uint4(ov[4 * j], ov[4 * j + 1], ov[4 * j + 2], ov[4 * j + 3]);
}

__global__ void wsplit_kernel(const float* __restrict__ w1, const float* __restrict__ w2)
{
    int i = blockIdx.x * 256 + threadIdx.x;
    if (i < 3 * 9 * 128 * 16) {
        int j = i & 15, rest = i >> 4;
        int o = rest & 127; rest >>= 7;
        int t = rest % 9, s = rest / 9;
        float va = w1[((size_t)o * 32 + 2 * j) * 9 + t];
        float vb = w1[((size_t)o * 32 + 2 * j + 1) * 9 + t];
        if (s == 2) { va -= bfround(va); vb -= bfround(vb); }
        g_w1e[i] = packbf(va, vb);
    } else {
        int i2 = i - 3 * 9 * 128 * 16;
        if (i2 < 3 * 9 * 32 * 64) {
            int j = i2 & 63, rest = i2 >> 6;
            int o = rest & 31; rest >>= 5;
            int t = rest % 9, s = rest / 9;
            float va = w2[((size_t)o * 128 + 2 * j) * 9 + t];
            float vb = w2[((size_t)o * 128 + 2 * j + 1) * 9 + t];
            if (s == 2) { va -= bfround(va); vb -= bfround(vb); }
            g_w2e[i2] = packbf(va, vb);
        }
    }
}

__global__ void border_kernel()
{
    int cell = blockIdx.x;
    int b = cell / 1032, e = cell % 1032;
    int gy, gx;
    if      (e < 258) { gy = 0;       gx = e; }
    else if (e < 516) { gy = 257;     gx = e - 258; }
    else if (e < 774) { gy = e - 516; gx = 0; }
    else              { gy = e - 774; gx = 257; }
    size_t p = (size_t)b * PPIX + (size_t)gy * PDIM + gx;
    int t = threadIdx.x;
    if (t < 32) g_xa1[p * 32 + t] = 0u;
    else        g_xa2[p * 128 + (t - 32)] = 0u;
}

// implicit-GEMM 3x3 conv on mma.sync + ldmatrix, 3-term bf16 split.
// B staging double-buffered via cp.async: load of tap t+1 overlaps mma of tap t.
template<int PASS>
__global__ void __launch_bounds__(256, 2) convmma_kernel(const float* __restrict__ bias)
{
    constexpr int COUT  = (PASS == 1) ? 128 : 32;
    constexpr int COUTB = (PASS == 1) ? 64  : 32;
    constexpr int KSEG  = (PASS == 1) ? 16  : 64;
    constexpr int KROW  = (PASS == 1) ? 32  : 128;
    constexpr int AP    = (PASS == 1) ? 20  : 68;
    constexpr int BP    = AP;
    constexpr int KC    = KSEG / 8;
    constexpr int NF    = COUTB / 8;
    constexpr int DP    = (PASS == 1) ? 68 : 36;
    constexpr int ASZ   = 340 * AP;
    constexpr int BSZ   = COUTB * BP;

    extern __shared__ float smf[];
    u32* sA = reinterpret_cast<u32*>(smf);
    u32* sB0 = sA + ASZ;
    u32* sB1 = sA + ASZ + BSZ;
    float* sD = smf;
    __shared__ float s_d[COUTB], s_b[COUTB], s_m[COUTB];

    const u32* gin = (PASS == 1) ? g_xa1 : g_xa2;
    const u32* we  = (PASS == 1) ? g_w1e : g_w2e;
    const float* dsc = (PASS == 1) ? g_d1 : g_d2;

    int zz = blockIdx.z;
    int bb = (PASS == 1) ? (zz >> 1) : zz;
    int og = (PASS == 1) ? (zz & 1)  : 0;
    int gy0 = blockIdx.y * 8, gx0 = blockIdx.x * 32;
    int tid = threadIdx.x;
    int w = tid >> 5, lane = tid & 31, g = lane >> 2, tig = lane & 3;
    int qrow = w >> 1;
    int lane7 = lane & 7, l8 = (lane >> 3) & 1, l16 = (lane >> 4) & 1;

    if (tid < COUTB) {
        s_d[tid] = dsc[bb * COUT + og * COUTB + tid];
        s_b[tid] = bias[og * COUTB + tid];
        s_m[tid] = (PASS == 1) ? g_st2[bb * CMID + og * COUTB + tid] * 1.4142135623730951f : 0.f;
    }

    u32 saBase = smem_u32(sA);
    u32 sbB[2] = { smem_u32(sB0), smem_u32(sB1) };
    int arow0 = qrow * 34 + (w & 1) * 16 + lane7 + l8 * 8;
    u32 akoff = (u32)(l16 * 16);
    int brow = lane7 + l16 * 8;
    u32 bkoff = (u32)(l8 * 16);

    size_t abase = (size_t)bb * PPIX;
    float acc[2][NF][4];
    #pragma unroll
    for (int rb = 0; rb < 2; ++rb)
        #pragma unroll
        for (int n = 0; n < NF; ++n)
            #pragma unroll
            for (int q = 0; q < 4; ++q) acc[rb][n][q] = 0.f;

    // stage A halo-union (direct loads; only 2x per block)
    auto stageA = [&](int segoff) {
        for (int i = tid; i < 340 * (KSEG / 4); i += 256) {
            int r = i / (KSEG / 4), w4 = i - r * (KSEG / 4);
            int sy = r / 34, sx = r - sy * 34;
            size_t p = abase + (size_t)(gy0 + sy) * PDIM + gx0 + sx;
            uint4 v = *reinterpret_cast<const uint4*>(gin + p * KROW + segoff + w4 * 4);
            *reinterpret_cast<uint4*>(sA + r * AP + w4 * 4) = v;
        }
    };
    // async-stage B tile for flat iteration it2 (si*9+tap) into buffer it2&1
    auto issueB = [&](int it2) {
        int si2 = it2 / 9, tap2 = it2 - 9 * si2;
        int s2 = (si2 == 0) ? 0 : (si2 == 1) ? 2 : 1;   // wh, wl, wh
        u32 dstb = sbB[it2 & 1];
        const u32* src = we + ((size_t)((s2 * 9 + tap2) * COUT + og * COUTB)) * KSEG;
        for (int i = tid; i < COUTB * (KSEG / 4); i += 256) {
            int o = i / (KSEG / 4), w4 = i - o * (KSEG / 4);
            cpasync16(dstb + (u32)((o * BP + w4 * 4) * 4), src + (size_t)o * KSEG + w4 * 4);
        }
        cp_commit();
    };

    stageA(0);          // xh
    issueB(0);

    #pragma unroll 1
    for (int it = 0; it < 27; ++it) {
        int si = it / 9, tap = it - 9 * si;
        cp_wait0();          // B(it) landed (this thread)
        __syncthreads();     // all threads: B(it) visible, compute(it-1) done
        if (it == 18) {      // switch A to xl (si=2); prior compute done
            stageA(KSEG);
        }
        if (it < 26) issueB(it + 1);   // overlaps with compute(it)
        if (it == 18) __syncthreads();
        int ty = tap / 3, tx = tap - 3 * ty;
        int arow = arow0 + ty * 34 + tx;
        u32 aAddr = saBase + (u32)(arow * AP) * 4u + akoff;
        u32 sbCur = sbB[it & 1];
        #pragma unroll
        for (int kc = 0; kc < KC; ++kc) {
            u32 a[2][4];
            ldsm4(a[0][0], a[0][1], a[0][2], a[0][3], aAddr + (u32)(kc * 32));
            ldsm4(a[1][0], a[1][1], a[1][2], a[1][3],
                  aAddr + (u32)(kc * 32) + (u32)(136 * AP * 4));
            #pragma unroll
            for (int j = 0; j < NF / 2; ++j) {
                u32 b0, b1, b2, b3;
                u32 bAddr = sbCur + (u32)(((j * 16 + brow) * BP + kc * 8) * 4) + bkoff;
                ldsm4(b0, b1, b2, b3, bAddr);
                mma16816(acc[0][2 * j],     a[0][0], a[0][1], a[0][2], a[0][3], b0, b1);
                mma16816(acc[0][2 * j + 1], a[0][0], a[0][1], a[0][2], a[0][3], b2, b3);
                mma16816(acc[1][2 * j],     a[1][0], a[1][1], a[1][2], a[1][3], b0, b1);
                mma16816(acc[1][2 * j + 1], a[1][0], a[1][1], a[1][2], a[1][3], b2, b3);
            }
        }
    }

    #pragma unroll 1
    for (int rb = 0; rb < 2; ++rb) {
        __syncthreads();
        int q0 = w * 16 + g;
        #pragma unroll
        for (int nf = 0; nf < NF; ++nf) {
            int cb = nf * 8 + 2 * tig;
            float d0 = s_d[cb], d1 = s_d[cb + 1];
            float b0 = s_b[cb], b1 = s_b[cb + 1];
            float y00 = acc[rb][nf][0] * d0 + b0, y01 = acc[rb][nf][1] * d1 + b1;
            float y10 = acc[rb][nf][2] * d0 + b0, y11 = acc[rb][nf][3] * d1 + b1;
            if (PASS == 1) {
                float m0 = s_m[cb], m1 = s_m[cb + 1];
                y00 = (y00 < 0.f ? 0.2f * y00 : y00) * m0;
                y01 = (y01 < 0.f ? 0.2f * y01 : y01) * m1;
                y10 = (y10 < 0.f ? 0.2f * y10 : y10) * m0;
                y11 = (y11 < 0.f ? 0.2f * y11 : y11) * m1;
            }
            sD[q0 * DP + cb] = y00; sD[q0 * DP + cb + 1] = y01;
            sD[(q0 + 8) * DP + cb] = y10; sD[(q0 + 8) * DP + cb + 1] = y11;
        }
        __syncthreads();
        if (PASS == 1) {
            for (int i = tid; i < 128 * 16; i += 256) {
                int q = i >> 4, t = i & 15;
                float4 y = *reinterpret_cast<const float4*>(sD + q * DP + 4 * t);
                u32 xh0 = packbf(y.x, y.y), xh1 = packbf(y.z, y.w);
                u32 xl0 = packbf(y.x - bfround(y.x), y.y - bfround(y.y));
                u32 xl1 = packbf(y.z - bfround(y.z), y.w - bfround(y.w));
                int gy = gy0 + rb * 4 + (q >> 5), gx = gx0 + (q & 31);
                u32* row = g_xa2 + (abase + (size_t)(gy + 1) * PDIM + gx + 1) * 128;
                int wj = og * 32 + 2 * t;
                *reinterpret_cast<u64*>(row + wj)      = (u64)xh0 | ((u64)xh1 << 32);
                *reinterpret_cast<u64*>(row + 64 + wj) = (u64)xl0 | ((u64)xl1 << 32);
            }
        } else {
            for (int i = tid; i < 32 * 128; i += 256) {
                int c = i >> 7, q = i & 127;
                float v = sD[q * DP + c];
                int gy = gy0 + rb * 4 + (q >> 5), gx = gx0 + (q & 31);
                g_tok[((size_t)bb * CH + c) * NPIX + gy * 256 + gx] = v;
            }
        }
    }
}

__device__ __forceinline__ void red2(float* p, float a, float b) {
    asm volatile("red.global.add.v2.f32 [%0], {%1, %2};"
                 :: "l"(p), "f"(a), "f"(b) : "memory");
}

__global__ void __launch_bounds__(256) recon_kernel(
    const float* __restrict__ coords, float* __restrict__ out, ResArr R)
{
    int idx = blockIdx.x * 256 + threadIdx.x;
    int b = idx >> 16, p = idx & 65535;
    float cx = coords[((size_t)b * NPIX + p) * 2 + 0];
    float cy = coords[((size_t)b * NPIX + p) * 2 + 1];
    float v[CH];
    #pragma unroll
    for (int c = 0; c < CH; ++c)
        v[c] = g_tok[(((size_t)b * CH + c) << 16) + p];
    #pragma unroll
    for (int l = 0; l < 16; ++l) {
        float rf = (float)R.r[l];
        float px = cx * rf, py = cy * rf;
        float fx0 = floorf(px), fy0 = floorf(py);
        float fx = px - fx0, fy = py - fy0;
        unsigned x0 = (unsigned)fx0, y0 = (unsigned)fy0;
        unsigned hy0 = y0 * PRIME, hy1 = (y0 + 1u) * PRIME;
        unsigned h00 = (x0 ^ hy0) & 65535u, h10 = ((x0 + 1u) ^ hy0) & 65535u;
        unsigned h01 = (x0 ^ hy1) & 65535u, h11 = ((x0 + 1u) ^ hy1) & 65535u;
        float w00 = (1.f - fx) * (1.f - fy), w10 = fx * (1.f - fy);
        float w01 = (1.f - fx) * fy,         w11 = fx * fy;
        float a0 = v[2 * l], a1 = v[2 * l + 1];
        float* ob = out + ((size_t)(b * 16 + l) << 17);
        red2(ob + 2 * h00, w00 * a0, w00 * a1);
        red2(ob + 2 * h10, w10 * a0, w10 * a1);
        red2(ob + 2 * h01, w01 * a0, w01 * a1);
        red2(ob + 2 * h11, w11 * a0, w11 * a1);
    }
}

extern "C" void kernel_launch(void* const* d_in, const int* in_sizes, int n_in,
                              void* d_out, int out_size)
{
    const float* inputs = (const float*)d_in[0];
    const float* s      = (const float*)d_in[1];
    const float* coords = (const float*)d_in[2];
    const float* w1_aff = (const float*)d_in[3];
    const float* b1_aff = (const float*)d_in[4];
    const float* w1     = (const float*)d_in[5];
    const float* b1     = (const float*)d_in[6];
    const float* w2_aff = (const float*)d_in[7];
    const float* b2_aff = (const float*)d_in[8];
    const float* w2     = (const float*)d_in[9];
    const float* b2     = (const float*)d_in[10];
    float* out = (float*)d_out;

    ResArr R;
    double bb = exp((log(256.0) - log(16.0)) / 15.0);
    for (int l = 0; l < 16; ++l)
        R.r[l] = (int)floor(16.0 * pow(bb, (double)l));

    const int SM1 = (340 * 20 + 2 * 64 * 20) * 4;   // 37440
    const int SM2 = (340 * 68 + 2 * 32 * 68) * 4;   // 109888
    cudaFuncSetAttribute(convmma_kernel<1>, cudaFuncAttributeMaxDynamicSharedMemorySize, SM1);
    cudaFuncSetAttribute(convmma_kernel<2>, cudaFuncAttributeMaxDynamicSharedMemorySize, SM2);

    cudaMemsetAsync(d_out, 0, (size_t)out_size * sizeof(float));

    styles_kernel<<<BATCH, CH + CMID>>>(s, w1_aff, b1_aff, w2_aff, b2_aff);
    demod_kernel<<<5, 256>>>(w1, w2);
    wsplit_kernel<<<432, 256>>>(w1, w2);
    retrieve_kernel<<<(BATCH * NPIX) / 256, 256>>>(inputs, coords, R);
    border_kernel<<<BATCH * 1032, 160>>>();

    dim3 cg1(8, 32, BATCH * 2);
    convmma_kernel<1><<<cg1, 256, SM1>>>(b1);
    dim3 cg2(8, 32, BATCH);
    convmma_kernel<2><<<cg2, 256, SM2>>>(b2);

    recon_kernel<<<(BATCH * NPIX) / 256, 256>>>(coords, out, R);
}